// round 1
// baseline (speedup 1.0000x reference)
#include <cuda_runtime.h>
#include <cuda_bf16.h>
#include <math.h>

// Problem constants
#define NN_ 2048
#define BB_ 8
#define TT_ 4
#define CC_ 64
#define HH_ 2

// ---------------- scratch (device globals; no allocation APIs) ----------------
__device__ float g_xT[4194304];      // [B,4,N,C]
__device__ float g_feat[16777216];   // [B,t,N,128] (max t=8)
__device__ float g_el[262144];
__device__ float g_er[262144];
__device__ float g_y[16777216];      // GAT out [B,2t,N,C] (max 16)
__device__ float g_z[16777216];      // LN out
__device__ float g_o1[12582912];     // [B,12,N,C]
__device__ float g_o1n[12582912];
__device__ float g_o2[12582912];
__device__ float g_wt1[20480];       // [k][ci][co]
__device__ float g_wt2[4096];        // [ci][co]
__device__ int   g_deg[2048];
__device__ int   g_rowptr[2049];
__device__ int   g_col[16384];

// ---------------- CSR build ----------------
__global__ void k_count(const int* __restrict__ dst, int* __restrict__ deg, int E) {
    int e = blockIdx.x * 256 + threadIdx.x;
    if (e < E) atomicAdd(&deg[dst[e]], 1);
}

__global__ void k_scan(const int* __restrict__ deg, int* __restrict__ rowptr) {
    // single block, 1024 threads, N=2048 elements, Hillis-Steele inclusive scan
    __shared__ int s[2048];
    int tid = threadIdx.x;
    s[tid] = deg[tid];
    s[tid + 1024] = deg[tid + 1024];
    __syncthreads();
    for (int off = 1; off < 2048; off <<= 1) {
        int i0 = tid, i1 = tid + 1024;
        int a0 = (i0 >= off) ? s[i0 - off] : 0;
        int a1 = (i1 >= off) ? s[i1 - off] : 0;
        __syncthreads();
        s[i0] += a0; s[i1] += a1;
        __syncthreads();
    }
    rowptr[tid + 1] = s[tid];
    rowptr[tid + 1025] = s[tid + 1024];
    if (tid == 0) rowptr[0] = 0;
}

__global__ void k_fill(const int* __restrict__ dst, const int* __restrict__ src,
                       const int* __restrict__ rowptr, int* __restrict__ col, int E) {
    // one warp per destination node, deterministic (edge-index) order
    int warp = (blockIdx.x * blockDim.x + threadIdx.x) >> 5;
    if (warp >= NN_) return;
    int lane = threadIdx.x & 31;
    int base = rowptr[warp];
    int cnt = 0;
    for (int e0 = 0; e0 < E; e0 += 32) {
        int e = e0 + lane;
        bool m = (e < E) && (dst[e] == warp);
        unsigned bal = __ballot_sync(0xFFFFFFFFu, m);
        if (m) {
            int pos = cnt + __popc(bal & ((1u << lane) - 1u));
            col[base + pos] = src[e];
        }
        cnt += __popc(bal);
    }
}

// ---------------- small transposes ----------------
__global__ void k_transpose_x(const float* __restrict__ x, float* __restrict__ xT) {
    int i = blockIdx.x * 256 + threadIdx.x;
    if (i >= BB_ * NN_ * TT_ * CC_) return;
    int c = i & 63;
    int t = (i >> 6) & 3;
    int n = (i >> 8) & 2047;
    int b = i >> 19;
    xT[((size_t)(b * 4 + t) * 2048 + n) * 64 + c] = x[i];
}

__global__ void k_tw1(const float* __restrict__ w, float* __restrict__ wt) {
    // w: [co][ci][5]  ->  wt: [k][ci][co]
    int i = blockIdx.x * 256 + threadIdx.x;
    if (i >= 20480) return;
    int k = i / 4096; int r = i % 4096; int ci = r >> 6; int co = r & 63;
    wt[i] = w[(co * 64 + ci) * 5 + k];
}

__global__ void k_tw2(const float* __restrict__ w, float* __restrict__ wt) {
    int i = blockIdx.x * 256 + threadIdx.x;
    if (i >= 4096) return;
    int ci = i >> 6, co = i & 63;
    wt[i] = w[co * 64 + ci];
}

// ---------------- GEMM: out[M,CO] = in[M,64] @ W[64,CO] (+bias) ----------------
template <int CO>
__global__ void k_gemm64(const float* __restrict__ in, const float* __restrict__ W,
                         const float* __restrict__ bias, float* __restrict__ out) {
    const int R = 8;
    size_t m0 = (size_t)blockIdx.x * R;
    int tid = threadIdx.x;
    __shared__ float xs[R * 64];
    for (int i = tid; i < R * 64; i += CO) xs[i] = in[m0 * 64 + i];
    __syncthreads();
    float acc[R];
#pragma unroll
    for (int r = 0; r < R; r++) acc[r] = 0.f;
#pragma unroll
    for (int k = 0; k < 64; k++) {
        float wv = W[k * CO + tid];
#pragma unroll
        for (int r = 0; r < R; r++) acc[r] += xs[r * 64 + k] * wv;
    }
    float bv = bias ? bias[tid] : 0.f;
#pragma unroll
    for (int r = 0; r < R; r++) out[(m0 + r) * CO + tid] = acc[r] + bv;
}

// ---------------- attention logits el/er ----------------
__global__ void k_elr(const float* __restrict__ feat, const float* __restrict__ al,
                      const float* __restrict__ ar, float* __restrict__ el,
                      float* __restrict__ er) {
    size_t m = blockIdx.x;
    int tid = threadIdx.x; // 128
    float v = feat[m * 128 + tid];
    float pl = v * al[tid];
    float pr = v * ar[tid];
    for (int o = 16; o; o >>= 1) {
        pl += __shfl_xor_sync(0xFFFFFFFFu, pl, o);
        pr += __shfl_xor_sync(0xFFFFFFFFu, pr, o);
    }
    __shared__ float sl[4], sr[4];
    if ((tid & 31) == 0) { sl[tid >> 5] = pl; sr[tid >> 5] = pr; }
    __syncthreads();
    if (tid < 2) {
        el[m * 2 + tid] = sl[2 * tid] + sl[2 * tid + 1];
        er[m * 2 + tid] = sr[2 * tid] + sr[2 * tid + 1];
    }
}

// ---------------- GAT aggregation (edge softmax + weighted sum + bias + relu) ----------------
__global__ void k_gat_agg(const float* __restrict__ feat, const float* __restrict__ el,
                          const float* __restrict__ er, const int* __restrict__ rowptr,
                          const int* __restrict__ col, const float* __restrict__ bias,
                          float* __restrict__ y, int t_in) {
    int n = blockIdx.x, b = blockIdx.y;
    int c = threadIdx.x; // 64 threads
    int r0 = rowptr[n], deg = rowptr[n + 1] - r0;
    __shared__ float red[2];
    for (int t = 0; t < t_in; t++) {
        for (int h = 0; h < 2; h++) {
            int rowbase = (b * t_in + t) * 2048;
            float er_d = er[(size_t)(rowbase + n) * 2 + h];
            // pass 1: max
            float mx = -3.0e38f;
            for (int j = c; j < deg; j += 64) {
                int s = col[r0 + j];
                float e = el[(size_t)(rowbase + s) * 2 + h] + er_d;
                e = e > 0.f ? e : 0.2f * e;
                mx = fmaxf(mx, e);
            }
            for (int o = 16; o; o >>= 1) mx = fmaxf(mx, __shfl_xor_sync(0xFFFFFFFFu, mx, o));
            if ((c & 31) == 0) red[c >> 5] = mx;
            __syncthreads();
            mx = fmaxf(red[0], red[1]);
            __syncthreads();
            // pass 2: sum of exp
            float sm = 0.f;
            for (int j = c; j < deg; j += 64) {
                int s = col[r0 + j];
                float e = el[(size_t)(rowbase + s) * 2 + h] + er_d;
                e = e > 0.f ? e : 0.2f * e;
                sm += __expf(e - mx);
            }
            for (int o = 16; o; o >>= 1) sm += __shfl_xor_sync(0xFFFFFFFFu, sm, o);
            if ((c & 31) == 0) red[c >> 5] = sm;
            __syncthreads();
            float inv = 1.f / (red[0] + red[1]);
            __syncthreads();
            // pass 3: weighted accumulation (fixed order -> deterministic)
            float acc = 0.f;
            for (int j = 0; j < deg; j++) {
                int s = col[r0 + j];
                float e = el[(size_t)(rowbase + s) * 2 + h] + er_d;
                e = e > 0.f ? e : 0.2f * e;
                float a = __expf(e - mx) * inv;
                acc += a * feat[((size_t)(rowbase + s) * 2 + h) * 64 + c];
            }
            acc += bias[h * 64 + c];
            float r = acc > 0.f ? acc : 0.f;
            y[((size_t)(b * (2 * t_in) + (t * 2 + h)) * 2048 + n) * 64 + c] = r;
        }
    }
}

// ---------------- LayerNorm over [N,C] per slice ----------------
__global__ void k_ln(const float* __restrict__ x, const float* __restrict__ w,
                     const float* __restrict__ bparm, float* __restrict__ out) {
    const int S = 2048 * 64;
    const float* xs = x + (size_t)blockIdx.x * S;
    float* os = out + (size_t)blockIdx.x * S;
    double s1 = 0.0, s2 = 0.0;
    for (int i = threadIdx.x; i < S; i += 1024) {
        float v = xs[i];
        s1 += v;
        s2 += (double)v * (double)v;
    }
    for (int o = 16; o; o >>= 1) {
        s1 += __shfl_xor_sync(0xFFFFFFFFu, s1, o);
        s2 += __shfl_xor_sync(0xFFFFFFFFu, s2, o);
    }
    __shared__ double sh1[32], sh2[32];
    int wid = threadIdx.x >> 5, lane = threadIdx.x & 31;
    if (!lane) { sh1[wid] = s1; sh2[wid] = s2; }
    __syncthreads();
    __shared__ float mean_s, rstd_s;
    if (threadIdx.x == 0) {
        double t1 = 0, t2 = 0;
        for (int k = 0; k < 32; k++) { t1 += sh1[k]; t2 += sh2[k]; }
        double mu = t1 / S;
        double var = t2 / S - mu * mu;
        mean_s = (float)mu;
        rstd_s = (float)rsqrt(var + 1e-5);
    }
    __syncthreads();
    float mu = mean_s, rs = rstd_s;
    for (int i = threadIdx.x; i < S; i += 1024)
        os[i] = (xs[i] - mu) * rs * w[i] + bparm[i];
}

// ---------------- temporal conv1 (K=5), register-tiled ----------------
__global__ void k_conv1(const float* __restrict__ z, const float* __restrict__ wt1,
                        const float* __restrict__ tb1, float* __restrict__ o1) {
    // grid: b*256 + ntile (8 nodes/tile); block 256
    int b = blockIdx.x >> 8;
    int nt = blockIdx.x & 255;
    int n0 = nt * 8;
    __shared__ float zs[16 * 64 * 8]; // [t][ci][nn] 32KB
    for (int i = threadIdx.x; i < 8192; i += 256) {
        int t = i >> 9;
        int r = i & 511;           // nn*64 + ci (global-contiguous chunk)
        int nn = r >> 6;
        int ci = r & 63;
        zs[(t * 64 + ci) * 8 + nn] = z[((size_t)((b * 16 + t) * 2048 + n0)) * 64 + r];
    }
    __syncthreads();
    int col = threadIdx.x & 15;        // co low 4 bits
    int nnp = (threadIdx.x >> 4) & 3;  // node pair
    int jg  = threadIdx.x >> 6;        // j group (3 j's each)
    float acc[4][3][2];
#pragma unroll
    for (int q = 0; q < 4; q++)
#pragma unroll
        for (int jj = 0; jj < 3; jj++) { acc[q][jj][0] = 0.f; acc[q][jj][1] = 0.f; }
#pragma unroll
    for (int k = 0; k < 5; k++) {
        for (int ci = 0; ci < 64; ci++) {
            const float* wp = &wt1[(k * 64 + ci) * 64 + col];
            float w0 = wp[0], w1 = wp[16], w2 = wp[32], w3 = wp[48];
#pragma unroll
            for (int jj = 0; jj < 3; jj++) {
                int t = jg * 3 + jj + k;
                float2 zv = *(const float2*)&zs[(t * 64 + ci) * 8 + nnp * 2];
                acc[0][jj][0] += zv.x * w0; acc[0][jj][1] += zv.y * w0;
                acc[1][jj][0] += zv.x * w1; acc[1][jj][1] += zv.y * w1;
                acc[2][jj][0] += zv.x * w2; acc[2][jj][1] += zv.y * w2;
                acc[3][jj][0] += zv.x * w3; acc[3][jj][1] += zv.y * w3;
            }
        }
    }
#pragma unroll
    for (int q = 0; q < 4; q++) {
        int co = col + q * 16;
        float bv = tb1[co];
#pragma unroll
        for (int jj = 0; jj < 3; jj++) {
            int j = jg * 3 + jj;
#pragma unroll
            for (int i2 = 0; i2 < 2; i2++) {
                int n = n0 + nnp * 2 + i2;
                o1[((size_t)((b * 12 + j) * 2048 + n)) * 64 + co] = acc[q][jj][i2] + bv;
            }
        }
    }
}

// ---------------- final FC with torch-faithful scrambled reshape ----------------
__global__ void k_fc(const float* __restrict__ o2, const float* __restrict__ fw,
                     const float* __restrict__ fb, float* __restrict__ out) {
    // grid: b*32 + q ; block 256. out row n' = 32*c + q, flat m = (n&63)*12 + j
    int b = blockIdx.x >> 5, q = blockIdx.x & 31;
    __shared__ float s[64 * 64]; // [rn][c]
    int c = threadIdx.x & 63;
    int rb = threadIdx.x >> 6; // r = rb*3 .. rb*3+2
    float acc[3] = {0.f, 0.f, 0.f};
    for (int j = 0; j < 12; j++) {
        __syncthreads();
        for (int i = threadIdx.x; i < 4096; i += 256)
            s[i] = o2[((size_t)((b * 12 + j) * 2048 + q * 64)) * 64 + i];
        __syncthreads();
        for (int rn = 0; rn < 64; rn++) {
            float v = s[rn * 64 + c];
#pragma unroll
            for (int rr = 0; rr < 3; rr++)
                acc[rr] += v * fw[(rb * 3 + rr) * 768 + rn * 12 + j];
        }
    }
    int np = 32 * c + q;
#pragma unroll
    for (int rr = 0; rr < 3; rr++) {
        int r = rb * 3 + rr;
        out[((size_t)b * 2048 + np) * 12 + r] = acc[rr] + fb[r];
    }
}

// ---------------- host ----------------
static void* sym(const void* s) {
    void* p = nullptr;
    cudaGetSymbolAddress(&p, s);
    return p;
}

extern "C" void kernel_launch(void* const* d_in, const int* in_sizes, int n_in,
                              void* d_out, int out_size) {
    const float* x   = (const float*)d_in[0];
    const int* src   = (const int*)d_in[1];
    const int* dst   = (const int*)d_in[2];
    const float* W1  = (const float*)d_in[3];
    const float* al1 = (const float*)d_in[4];
    const float* ar1 = (const float*)d_in[5];
    const float* b1  = (const float*)d_in[6];
    const float* W2  = (const float*)d_in[7];
    const float* al2 = (const float*)d_in[8];
    const float* ar2 = (const float*)d_in[9];
    const float* b2  = (const float*)d_in[10];
    const float* ln1w = (const float*)d_in[11];
    const float* ln1b = (const float*)d_in[12];
    const float* ln2w = (const float*)d_in[13];
    const float* ln2b = (const float*)d_in[14];
    const float* tc1w = (const float*)d_in[15];
    const float* tc1b = (const float*)d_in[16];
    const float* ln3w = (const float*)d_in[17];
    const float* ln3b = (const float*)d_in[18];
    const float* tc2w = (const float*)d_in[19];
    const float* tc2b = (const float*)d_in[20];
    const float* fcw  = (const float*)d_in[21];
    const float* fcb  = (const float*)d_in[22];
    int E = in_sizes[1];

    float* xT   = (float*)sym(g_xT);
    float* feat = (float*)sym(g_feat);
    float* el   = (float*)sym(g_el);
    float* er   = (float*)sym(g_er);
    float* y    = (float*)sym(g_y);
    float* z    = (float*)sym(g_z);
    float* o1   = (float*)sym(g_o1);
    float* o1n  = (float*)sym(g_o1n);
    float* o2   = (float*)sym(g_o2);
    float* wt1  = (float*)sym(g_wt1);
    float* wt2  = (float*)sym(g_wt2);
    int* deg    = (int*)sym(g_deg);
    int* rowptr = (int*)sym(g_rowptr);
    int* col    = (int*)sym(g_col);
    float* out  = (float*)d_out;

    // CSR build (deterministic)
    cudaMemsetAsync(deg, 0, 2048 * sizeof(int), 0);
    k_count<<<(E + 255) / 256, 256>>>(dst, deg, E);
    k_scan<<<1, 1024>>>(deg, rowptr);
    k_fill<<<256, 256>>>(dst, src, rowptr, col, E);

    // weight transposes
    k_tw1<<<80, 256>>>(tc1w, wt1);
    k_tw2<<<16, 256>>>(tc2w, wt2);

    // x -> [B,T,N,C]
    k_transpose_x<<<16384, 256>>>(x, xT);

    // ---- GAT layer 1 (t_in = 4) ----
    k_gemm64<128><<<65536 / 8, 128>>>(xT, W1, nullptr, feat);
    k_elr<<<65536, 128>>>(feat, al1, ar1, el, er);
    {
        dim3 g(2048, 8);
        k_gat_agg<<<g, 64>>>(feat, el, er, rowptr, col, b1, y, 4);
    }
    k_ln<<<64, 1024>>>(y, ln1w, ln1b, z);

    // ---- GAT layer 2 (t_in = 8) ----
    k_gemm64<128><<<131072 / 8, 128>>>(z, W2, nullptr, feat);
    k_elr<<<131072, 128>>>(feat, al2, ar2, el, er);
    {
        dim3 g(2048, 8);
        k_gat_agg<<<g, 64>>>(feat, el, er, rowptr, col, b2, y, 8);
    }
    k_ln<<<128, 1024>>>(y, ln2w, ln2b, z);

    // ---- output layer ----
    k_conv1<<<2048, 256>>>(z, wt1, tc1b, o1);
    k_ln<<<96, 1024>>>(o1, ln3w, ln3b, o1n);
    k_gemm64<64><<<196608 / 8, 64>>>(o1n, wt2, tc2b, o2);
    k_fc<<<256, 256>>>(o2, fcw, fcb, out);
}

// round 2
// speedup vs baseline: 1.3235x; 1.3235x over previous
#include <cuda_runtime.h>
#include <cuda_bf16.h>
#include <math.h>

#define NN_ 2048
#define BB_ 8

typedef unsigned long long ull;

__device__ __forceinline__ ull pk2(float x, float y) {
    ull r; asm("mov.b64 %0,{%1,%2};" : "=l"(r) : "f"(x), "f"(y)); return r;
}
__device__ __forceinline__ ull dup2(float x) { return pk2(x, x); }
__device__ __forceinline__ void fma2(ull& d, ull a, ull b) {
    asm("fma.rn.f32x2 %0,%1,%2,%0;" : "+l"(d) : "l"(a), "l"(b));
}
__device__ __forceinline__ float2 unpk2(ull v) {
    float2 f; asm("mov.b64 {%0,%1},%2;" : "=f"(f.x), "=f"(f.y) : "l"(v)); return f;
}

// ---------------- scratch ----------------
__device__ float g_xT[4194304];      // [B,4,N,C]
__device__ float g_feat[16777216];   // [B,t,N,128]
__device__ float g_el[262144];
__device__ float g_er[262144];
__device__ float g_alpha[2097152];   // [combo(<=128)][E]
__device__ float g_y[16777216];
__device__ float g_z[16777216];
__device__ float g_o1[12582912];
__device__ float g_o1n[12582912];
__device__ float g_o2[12582912];
__device__ float g_wt1[20480];       // [k][ci][col16][q4]
__device__ float g_wt2[4096];        // [ci][co]
__device__ int   g_deg[2048];
__device__ int   g_rowptr[2049];
__device__ int   g_col[16384];

// ---------------- CSR build ----------------
__global__ void k_count(const int* __restrict__ dst, int* __restrict__ deg, int E) {
    int e = blockIdx.x * 256 + threadIdx.x;
    if (e < E) atomicAdd(&deg[dst[e]], 1);
}

__global__ void k_scan(const int* __restrict__ deg, int* __restrict__ rowptr) {
    __shared__ int s[2048];
    int tid = threadIdx.x;
    s[tid] = deg[tid];
    s[tid + 1024] = deg[tid + 1024];
    __syncthreads();
    for (int off = 1; off < 2048; off <<= 1) {
        int i0 = tid, i1 = tid + 1024;
        int a0 = (i0 >= off) ? s[i0 - off] : 0;
        int a1 = (i1 >= off) ? s[i1 - off] : 0;
        __syncthreads();
        s[i0] += a0; s[i1] += a1;
        __syncthreads();
    }
    rowptr[tid + 1] = s[tid];
    rowptr[tid + 1025] = s[tid + 1024];
    if (tid == 0) rowptr[0] = 0;
}

__global__ void k_fill(const int* __restrict__ dst, const int* __restrict__ src,
                       const int* __restrict__ rowptr, int* __restrict__ col, int E) {
    int warp = (blockIdx.x * blockDim.x + threadIdx.x) >> 5;
    if (warp >= NN_) return;
    int lane = threadIdx.x & 31;
    int base = rowptr[warp];
    int cnt = 0;
    for (int e0 = 0; e0 < E; e0 += 32) {
        int e = e0 + lane;
        bool m = (e < E) && (dst[e] == warp);
        unsigned bal = __ballot_sync(0xFFFFFFFFu, m);
        if (m) {
            int pos = cnt + __popc(bal & ((1u << lane) - 1u));
            col[base + pos] = src[e];
        }
        cnt += __popc(bal);
    }
}

// ---------------- transposes ----------------
__global__ void k_transpose_x(const float* __restrict__ x, float* __restrict__ xT) {
    int i = blockIdx.x * 256 + threadIdx.x;
    if (i >= BB_ * NN_ * 4 * 64) return;
    int c = i & 63;
    int t = (i >> 6) & 3;
    int n = (i >> 8) & 2047;
    int b = i >> 19;
    xT[((size_t)(b * 4 + t) * 2048 + n) * 64 + c] = x[i];
}

__global__ void k_tw1(const float* __restrict__ w, float* __restrict__ wt) {
    // w: [co][ci][5]  ->  wt: [k][ci][col16][q4]  (co = q*16 + col)
    int i = blockIdx.x * 256 + threadIdx.x;
    if (i >= 20480) return;
    int q = i & 3;
    int colc = (i >> 2) & 15;
    int ci = (i >> 6) & 63;
    int k = i >> 12;
    int co = q * 16 + colc;
    wt[i] = w[(co * 64 + ci) * 5 + k];
}

__global__ void k_tw2(const float* __restrict__ w, float* __restrict__ wt) {
    int i = blockIdx.x * 256 + threadIdx.x;
    if (i >= 4096) return;
    int ci = i >> 6, co = i & 63;
    wt[i] = w[co * 64 + ci];
}

// ---------------- GEMM with f32x2, optional fused el/er ----------------
template <int CO, bool ELR>
__global__ void k_gemm64f(const float* __restrict__ in, const float* __restrict__ W,
                          const float* __restrict__ bias, float* __restrict__ out,
                          const float* __restrict__ al, const float* __restrict__ ar,
                          float* __restrict__ el, float* __restrict__ er) {
    const int R2 = 16;  // rows per block (8 packed pairs)
    size_t m0 = (size_t)blockIdx.x * R2;
    int tid = threadIdx.x;  // = co
    __shared__ float xs2[64 * 16];  // [k][row]
    for (int i = tid; i < R2 * 64; i += CO) {
        int r = i >> 6, k = i & 63;
        xs2[k * 16 + r] = in[(m0 + r) * 64 + k];
    }
    __syncthreads();
    ull acc[8];
#pragma unroll
    for (int p = 0; p < 8; p++) acc[p] = 0ull;
#pragma unroll
    for (int k = 0; k < 64; k++) {
        ull wd = dup2(W[k * CO + tid]);
#pragma unroll
        for (int p = 0; p < 8; p++) {
            ull xv = *(const ull*)&xs2[k * 16 + 2 * p];
            fma2(acc[p], xv, wd);
        }
    }
    float bv = bias ? bias[tid] : 0.f;
    if (ELR) {
        __shared__ float ys[16 * 128];
#pragma unroll
        for (int p = 0; p < 8; p++) {
            float2 v = unpk2(acc[p]);
            out[(m0 + 2 * p) * CO + tid] = v.x;
            out[(m0 + 2 * p + 1) * CO + tid] = v.y;
            ys[(2 * p) * 128 + tid] = v.x;
            ys[(2 * p + 1) * 128 + tid] = v.y;
        }
        __syncthreads();
        // 128 threads: (r, h, q) -> 16 rows x 2 heads x 4 quads
        int r = tid >> 3;
        int h = (tid >> 2) & 1;
        int q = tid & 3;
        float sl = 0.f, sr = 0.f;
#pragma unroll
        for (int i = 0; i < 16; i++) {
            int co = h * 64 + q * 16 + i;
            float f = ys[r * 128 + co];
            sl += f * al[co];
            sr += f * ar[co];
        }
        sl += __shfl_xor_sync(0xFFFFFFFFu, sl, 1);
        sl += __shfl_xor_sync(0xFFFFFFFFu, sl, 2);
        sr += __shfl_xor_sync(0xFFFFFFFFu, sr, 1);
        sr += __shfl_xor_sync(0xFFFFFFFFu, sr, 2);
        if (q == 0) {
            el[(m0 + r) * 2 + h] = sl;
            er[(m0 + r) * 2 + h] = sr;
        }
    } else {
#pragma unroll
        for (int p = 0; p < 8; p++) {
            float2 v = unpk2(acc[p]);
            out[(m0 + 2 * p) * CO + tid] = v.x + bv;
            out[(m0 + 2 * p + 1) * CO + tid] = v.y + bv;
        }
    }
}

// ---------------- edge softmax alpha (warp per (n,b)) ----------------
__global__ void k_alpha(const float* __restrict__ el, const float* __restrict__ er,
                        const int* __restrict__ rowptr, const int* __restrict__ col,
                        float* __restrict__ alpha, int t_in, int Etot) {
    int gw = blockIdx.x * 8 + (threadIdx.x >> 5);
    int n = gw >> 3, b = gw & 7;
    int lane = threadIdx.x & 31;
    int r0 = rowptr[n], deg = rowptr[n + 1] - r0;
    if (deg <= 32) {
        int s = (lane < deg) ? col[r0 + lane] : 0;
        for (int t = 0; t < t_in; t++) {
            int base = (b * t_in + t) * 2048;
#pragma unroll
            for (int h = 0; h < 2; h++) {
                float erd = er[(size_t)(base + n) * 2 + h];
                float e = -3.0e38f;
                if (lane < deg) {
                    float v = el[(size_t)(base + s) * 2 + h] + erd;
                    e = v > 0.f ? v : 0.2f * v;
                }
                float mx = e;
                for (int o = 16; o; o >>= 1) mx = fmaxf(mx, __shfl_xor_sync(0xFFFFFFFFu, mx, o));
                float a = (lane < deg) ? __expf(e - mx) : 0.f;
                float sm = a;
                for (int o = 16; o; o >>= 1) sm += __shfl_xor_sync(0xFFFFFFFFu, sm, o);
                if (lane < deg)
                    alpha[(size_t)((b * t_in + t) * 2 + h) * Etot + r0 + lane] = a / sm;
            }
        }
    } else {
        for (int t = 0; t < t_in; t++) {
            int base = (b * t_in + t) * 2048;
            for (int h = 0; h < 2; h++) {
                float erd = er[(size_t)(base + n) * 2 + h];
                float mx = -3.0e38f;
                for (int j = lane; j < deg; j += 32) {
                    float v = el[(size_t)(base + col[r0 + j]) * 2 + h] + erd;
                    v = v > 0.f ? v : 0.2f * v;
                    mx = fmaxf(mx, v);
                }
                for (int o = 16; o; o >>= 1) mx = fmaxf(mx, __shfl_xor_sync(0xFFFFFFFFu, mx, o));
                float sm = 0.f;
                for (int j = lane; j < deg; j += 32) {
                    float v = el[(size_t)(base + col[r0 + j]) * 2 + h] + erd;
                    v = v > 0.f ? v : 0.2f * v;
                    sm += __expf(v - mx);
                }
                for (int o = 16; o; o >>= 1) sm += __shfl_xor_sync(0xFFFFFFFFu, sm, o);
                for (int j = lane; j < deg; j += 32) {
                    float v = el[(size_t)(base + col[r0 + j]) * 2 + h] + erd;
                    v = v > 0.f ? v : 0.2f * v;
                    alpha[(size_t)((b * t_in + t) * 2 + h) * Etot + r0 + j] = __expf(v - mx) / sm;
                }
            }
        }
    }
}

// ---------------- gather: y = sum_j alpha_j * feat[col_j], +bias, relu ----------------
template <int TIN>
__global__ void k_gather(const float* __restrict__ feat, const float* __restrict__ alpha,
                         const int* __restrict__ rowptr, const int* __restrict__ col,
                         const float* __restrict__ bias, float* __restrict__ y, int Etot) {
    int n = blockIdx.x, b = blockIdx.y;
    int c = threadIdx.x;  // 64
    int r0 = rowptr[n], deg = rowptr[n + 1] - r0;
    float acc[TIN * 2];
#pragma unroll
    for (int i = 0; i < TIN * 2; i++) acc[i] = 0.f;
    for (int j = 0; j < deg; j++) {
        int s = col[r0 + j];
#pragma unroll
        for (int t = 0; t < TIN; t++) {
#pragma unroll
            for (int h = 0; h < 2; h++) {
                float a = alpha[(size_t)((b * TIN + t) * 2 + h) * Etot + r0 + j];
                float f = feat[(size_t)((b * TIN + t) * 2048 + s) * 128 + h * 64 + c];
                acc[t * 2 + h] += a * f;
            }
        }
    }
#pragma unroll
    for (int t = 0; t < TIN; t++) {
#pragma unroll
        for (int h = 0; h < 2; h++) {
            float v = acc[t * 2 + h] + bias[h * 64 + c];
            v = v > 0.f ? v : 0.f;
            y[((size_t)(b * 2 * TIN + t * 2 + h) * 2048 + n) * 64 + c] = v;
        }
    }
}

// ---------------- LayerNorm over [N,C] per slice ----------------
__global__ void k_ln(const float* __restrict__ x, const float* __restrict__ w,
                     const float* __restrict__ bparm, float* __restrict__ out) {
    const int S = 2048 * 64;
    const float* xs = x + (size_t)blockIdx.x * S;
    float* os = out + (size_t)blockIdx.x * S;
    double s1 = 0.0, s2 = 0.0;
    for (int i = threadIdx.x; i < S; i += 1024) {
        float v = xs[i];
        s1 += v;
        s2 += (double)v * (double)v;
    }
    for (int o = 16; o; o >>= 1) {
        s1 += __shfl_xor_sync(0xFFFFFFFFu, s1, o);
        s2 += __shfl_xor_sync(0xFFFFFFFFu, s2, o);
    }
    __shared__ double sh1[32], sh2[32];
    int wid = threadIdx.x >> 5, lane = threadIdx.x & 31;
    if (!lane) { sh1[wid] = s1; sh2[wid] = s2; }
    __syncthreads();
    __shared__ float mean_s, rstd_s;
    if (threadIdx.x == 0) {
        double t1 = 0, t2 = 0;
        for (int k = 0; k < 32; k++) { t1 += sh1[k]; t2 += sh2[k]; }
        double mu = t1 / S;
        double var = t2 / S - mu * mu;
        mean_s = (float)mu;
        rstd_s = (float)rsqrt(var + 1e-5);
    }
    __syncthreads();
    float mu = mean_s, rs = rstd_s;
    for (int i = threadIdx.x; i < S; i += 1024)
        os[i] = (xs[i] - mu) * rs * w[i] + bparm[i];
}

// ---------------- temporal conv1 (K=5), f32x2 register-tiled ----------------
__global__ void k_conv1(const float* __restrict__ z, const float* __restrict__ wt1,
                        const float* __restrict__ tb1, float* __restrict__ o1) {
    int b = blockIdx.x >> 8;
    int nt = blockIdx.x & 255;
    int n0 = nt * 8;
    __shared__ float zs[16 * 64 * 8];  // [t][ci][nn]
    for (int i = threadIdx.x; i < 8192; i += 256) {
        int t = i >> 9;
        int r = i & 511;
        int nn = r >> 6;
        int ci = r & 63;
        zs[(t * 64 + ci) * 8 + nn] = z[((size_t)((b * 16 + t) * 2048 + n0)) * 64 + r];
    }
    __syncthreads();
    int colc = threadIdx.x & 15;
    int nnp = (threadIdx.x >> 4) & 3;
    int jg = threadIdx.x >> 6;
    ull acc[4][3];
#pragma unroll
    for (int q = 0; q < 4; q++)
#pragma unroll
        for (int jj = 0; jj < 3; jj++) acc[q][jj] = 0ull;
#pragma unroll
    for (int k = 0; k < 5; k++) {
        for (int ci = 0; ci < 64; ci++) {
            float4 w4 = *(const float4*)&wt1[((k * 64 + ci) * 16 + colc) * 4];
            ull w0 = dup2(w4.x), w1 = dup2(w4.y), w2 = dup2(w4.z), w3 = dup2(w4.w);
#pragma unroll
            for (int jj = 0; jj < 3; jj++) {
                int t = jg * 3 + jj + k;
                ull zv = *(const ull*)&zs[(t * 64 + ci) * 8 + nnp * 2];
                fma2(acc[0][jj], zv, w0);
                fma2(acc[1][jj], zv, w1);
                fma2(acc[2][jj], zv, w2);
                fma2(acc[3][jj], zv, w3);
            }
        }
    }
#pragma unroll
    for (int q = 0; q < 4; q++) {
        int co = q * 16 + colc;
        float bv = tb1[co];
#pragma unroll
        for (int jj = 0; jj < 3; jj++) {
            int j = jg * 3 + jj;
            float2 v = unpk2(acc[q][jj]);
            int n = n0 + nnp * 2;
            o1[((size_t)((b * 12 + j) * 2048 + n)) * 64 + co] = v.x + bv;
            o1[((size_t)((b * 12 + j) * 2048 + n + 1)) * 64 + co] = v.y + bv;
        }
    }
}

// ---------------- final FC with torch-faithful scrambled reshape ----------------
__global__ void k_fc(const float* __restrict__ o2, const float* __restrict__ fw,
                     const float* __restrict__ fb, float* __restrict__ out) {
    int b = blockIdx.x >> 5, q = blockIdx.x & 31;
    __shared__ float s[64 * 64];
    int c = threadIdx.x & 63;
    int rb = threadIdx.x >> 6;
    float acc[3] = {0.f, 0.f, 0.f};
    for (int j = 0; j < 12; j++) {
        __syncthreads();
        for (int i = threadIdx.x; i < 4096; i += 256)
            s[i] = o2[((size_t)((b * 12 + j) * 2048 + q * 64)) * 64 + i];
        __syncthreads();
        for (int rn = 0; rn < 64; rn++) {
            float v = s[rn * 64 + c];
#pragma unroll
            for (int rr = 0; rr < 3; rr++)
                acc[rr] += v * fw[(rb * 3 + rr) * 768 + rn * 12 + j];
        }
    }
    int np = 32 * c + q;
#pragma unroll
    for (int rr = 0; rr < 3; rr++) {
        int r = rb * 3 + rr;
        out[((size_t)b * 2048 + np) * 12 + r] = acc[rr] + fb[r];
    }
}

// ---------------- host ----------------
static void* sym(const void* s) {
    void* p = nullptr;
    cudaGetSymbolAddress(&p, s);
    return p;
}

extern "C" void kernel_launch(void* const* d_in, const int* in_sizes, int n_in,
                              void* d_out, int out_size) {
    const float* x = (const float*)d_in[0];
    const int* src = (const int*)d_in[1];
    const int* dst = (const int*)d_in[2];
    const float* W1 = (const float*)d_in[3];
    const float* al1 = (const float*)d_in[4];
    const float* ar1 = (const float*)d_in[5];
    const float* b1 = (const float*)d_in[6];
    const float* W2 = (const float*)d_in[7];
    const float* al2 = (const float*)d_in[8];
    const float* ar2 = (const float*)d_in[9];
    const float* b2 = (const float*)d_in[10];
    const float* ln1w = (const float*)d_in[11];
    const float* ln1b = (const float*)d_in[12];
    const float* ln2w = (const float*)d_in[13];
    const float* ln2b = (const float*)d_in[14];
    const float* tc1w = (const float*)d_in[15];
    const float* tc1b = (const float*)d_in[16];
    const float* ln3w = (const float*)d_in[17];
    const float* ln3b = (const float*)d_in[18];
    const float* tc2w = (const float*)d_in[19];
    const float* tc2b = (const float*)d_in[20];
    const float* fcw = (const float*)d_in[21];
    const float* fcb = (const float*)d_in[22];
    int E = in_sizes[1];

    float* xT = (float*)sym(g_xT);
    float* feat = (float*)sym(g_feat);
    float* el = (float*)sym(g_el);
    float* er = (float*)sym(g_er);
    float* alpha = (float*)sym(g_alpha);
    float* y = (float*)sym(g_y);
    float* z = (float*)sym(g_z);
    float* o1 = (float*)sym(g_o1);
    float* o1n = (float*)sym(g_o1n);
    float* o2 = (float*)sym(g_o2);
    float* wt1 = (float*)sym(g_wt1);
    float* wt2 = (float*)sym(g_wt2);
    int* deg = (int*)sym(g_deg);
    int* rowptr = (int*)sym(g_rowptr);
    int* col = (int*)sym(g_col);
    float* out = (float*)d_out;

    cudaMemsetAsync(deg, 0, 2048 * sizeof(int), 0);
    k_count<<<(E + 255) / 256, 256>>>(dst, deg, E);
    k_scan<<<1, 1024>>>(deg, rowptr);
    k_fill<<<256, 256>>>(dst, src, rowptr, col, E);
    k_transpose_x<<<16384, 256>>>(x, xT);

    // ---- GAT layer 1 ----
    k_gemm64f<128, true><<<65536 / 16, 128>>>(xT, W1, nullptr, feat, al1, ar1, el, er);
    k_alpha<<<2048, 256>>>(el, er, rowptr, col, alpha, 4, E);
    {
        dim3 g(2048, 8);
        k_gather<4><<<g, 64>>>(feat, alpha, rowptr, col, b1, y, E);
    }
    k_ln<<<64, 1024>>>(y, ln1w, ln1b, z);

    // ---- GAT layer 2 ----
    k_gemm64f<128, true><<<131072 / 16, 128>>>(z, W2, nullptr, feat, al2, ar2, el, er);
    k_alpha<<<2048, 256>>>(el, er, rowptr, col, alpha, 8, E);
    {
        dim3 g(2048, 8);
        k_gather<8><<<g, 64>>>(feat, alpha, rowptr, col, b2, y, E);
    }
    k_ln<<<128, 1024>>>(y, ln2w, ln2b, z);

    // ---- output layer ----
    k_tw1<<<80, 256>>>(tc1w, wt1);
    k_tw2<<<16, 256>>>(tc2w, wt2);
    k_conv1<<<2048, 256>>>(z, wt1, tc1b, o1);
    k_ln<<<96, 1024>>>(o1, ln3w, ln3b, o1n);
    k_gemm64f<64, false><<<196608 / 16, 64>>>(o1n, wt2, tc2b, o2, nullptr, nullptr, nullptr, nullptr);
    k_fc<<<256, 256>>>(o2, fcw, fcb, out);
}

// round 4
// speedup vs baseline: 1.4112x; 1.0663x over previous
#include <cuda_runtime.h>
#include <cuda_bf16.h>
#include <math.h>

#define NN_ 2048
#define BB_ 8

typedef unsigned long long ull;

__device__ __forceinline__ ull pk2(float x, float y) {
    ull r; asm("mov.b64 %0,{%1,%2};" : "=l"(r) : "f"(x), "f"(y)); return r;
}
__device__ __forceinline__ ull dup2(float x) { return pk2(x, x); }
__device__ __forceinline__ void fma2(ull& d, ull a, ull b) {
    asm("fma.rn.f32x2 %0,%1,%2,%0;" : "+l"(d) : "l"(a), "l"(b));
}
__device__ __forceinline__ float2 unpk2(ull v) {
    float2 f; asm("mov.b64 {%0,%1},%2;" : "=f"(f.x), "=f"(f.y) : "l"(v)); return f;
}

// ---------------- scratch ----------------
__device__ float g_xT[4194304];      // [B,4,N,C]
__device__ float g_feat[16777216];   // [B,t,N,128]
__device__ float g_el[262144];
__device__ float g_er[262144];
__device__ float g_alpha[2097152];
__device__ float g_y[16777216];      // raw GAT1 out [B,8,N,C]
__device__ float g_z[16777216];      // raw GAT2 out [B,16,N,C]
__device__ float g_o1[12582912];     // raw conv1 out [B,12,N,C]
__device__ float g_o2[12582912];
__device__ float g_wt1[20480];       // [k][ci][col16][q4]
__device__ float g_wt2[4096];        // [ci][co]
__device__ double g_stat[1024];      // [slice<=128][4 part][2]
__device__ int   g_deg[2048];
__device__ int   g_rowptr[2049];
__device__ int   g_col[16384];

// ---------------- transpose x (+ zero deg) : LAUNCH #1 ----------------
__global__ void k_transpose_x(const float* __restrict__ x, float* __restrict__ xT,
                              int* __restrict__ deg) {
    int i = blockIdx.x * 256 + threadIdx.x;
    if (i < 2048) deg[i] = 0;
    if (i >= BB_ * NN_ * 4 * 64) return;
    int c = i & 63;
    int t = (i >> 6) & 3;
    int n = (i >> 8) & 2047;
    int b = i >> 19;
    xT[((size_t)(b * 4 + t) * 2048 + n) * 64 + c] = x[i];
}

// ---------------- CSR build ----------------
__global__ void k_count(const int* __restrict__ dst, int* __restrict__ deg, int E) {
    int e = blockIdx.x * 256 + threadIdx.x;
    if (e < E) atomicAdd(&deg[dst[e]], 1);
}

__global__ void k_scan(const int* __restrict__ deg, int* __restrict__ rowptr) {
    __shared__ int s[2048];
    int tid = threadIdx.x;
    s[tid] = deg[tid];
    s[tid + 1024] = deg[tid + 1024];
    __syncthreads();
    for (int off = 1; off < 2048; off <<= 1) {
        int i0 = tid, i1 = tid + 1024;
        int a0 = (i0 >= off) ? s[i0 - off] : 0;
        int a1 = (i1 >= off) ? s[i1 - off] : 0;
        __syncthreads();
        s[i0] += a0; s[i1] += a1;
        __syncthreads();
    }
    rowptr[tid + 1] = s[tid];
    rowptr[tid + 1025] = s[tid + 1024];
    if (tid == 0) rowptr[0] = 0;
}

__global__ void k_fill(const int* __restrict__ dst, const int* __restrict__ src,
                       const int* __restrict__ rowptr, int* __restrict__ col, int E) {
    int warp = (blockIdx.x * blockDim.x + threadIdx.x) >> 5;
    if (warp >= NN_) return;
    int lane = threadIdx.x & 31;
    int base = rowptr[warp];
    int cnt = 0;
    for (int e0 = 0; e0 < E; e0 += 32) {
        int e = e0 + lane;
        bool m = (e < E) && (dst[e] == warp);
        unsigned bal = __ballot_sync(0xFFFFFFFFu, m);
        if (m) {
            int pos = cnt + __popc(bal & ((1u << lane) - 1u));
            col[base + pos] = src[e];
        }
        cnt += __popc(bal);
    }
}

// ---------------- weight transposes ----------------
__global__ void k_tw1(const float* __restrict__ w, float* __restrict__ wt) {
    int i = blockIdx.x * 256 + threadIdx.x;
    if (i >= 20480) return;
    int q = i & 3;
    int colc = (i >> 2) & 15;
    int ci = (i >> 6) & 63;
    int k = i >> 12;
    int co = q * 16 + colc;
    wt[i] = w[(co * 64 + ci) * 5 + k];
}

__global__ void k_tw2(const float* __restrict__ w, float* __restrict__ wt) {
    int i = blockIdx.x * 256 + threadIdx.x;
    if (i >= 4096) return;
    int ci = i >> 6, co = i & 63;
    wt[i] = w[co * 64 + ci];
}

// ---------------- LN partial stats ----------------
__global__ void k_lnpart(const float* __restrict__ x, double* __restrict__ stat) {
    int slice = blockIdx.x >> 2, q = blockIdx.x & 3;
    const float* xs = x + (size_t)slice * 131072 + q * 32768;
    double s1 = 0.0, s2 = 0.0;
    for (int i = threadIdx.x; i < 32768; i += 1024) {
        float v = xs[i];
        s1 += v;
        s2 += (double)v * (double)v;
    }
    for (int o = 16; o; o >>= 1) {
        s1 += __shfl_xor_sync(0xFFFFFFFFu, s1, o);
        s2 += __shfl_xor_sync(0xFFFFFFFFu, s2, o);
    }
    __shared__ double sh1[32], sh2[32];
    int wid = threadIdx.x >> 5, lane = threadIdx.x & 31;
    if (!lane) { sh1[wid] = s1; sh2[wid] = s2; }
    __syncthreads();
    if (threadIdx.x == 0) {
        double t1 = 0, t2 = 0;
        for (int k = 0; k < 32; k++) { t1 += sh1[k]; t2 += sh2[k]; }
        stat[slice * 8 + q * 2] = t1;
        stat[slice * 8 + q * 2 + 1] = t2;
    }
}

__device__ __forceinline__ void ln_combine(const double* __restrict__ stat, int slice,
                                           float& mu, float& rs) {
    double t1 = 0, t2 = 0;
#pragma unroll
    for (int q = 0; q < 4; q++) {
        t1 += stat[slice * 8 + q * 2];
        t2 += stat[slice * 8 + q * 2 + 1];
    }
    double m = t1 / 131072.0;
    double var = t2 / 131072.0 - m * m;
    mu = (float)m;
    rs = (float)rsqrt(var + 1e-5);
}

// ---------------- GEMM: f32x2, 2 co/thread, optional LN-in + el/er-out ----------------
// smem: one buffer aliased as xs ([k][row], 64*ROWS) then (ELR only) ys ([row][128]).
template <int CO, bool ELR, bool LNIN>
__global__ void k_gemm(const float* __restrict__ in, const float* __restrict__ W,
                       const float* __restrict__ bias, float* __restrict__ out,
                       const float* __restrict__ al, const float* __restrict__ ar,
                       float* __restrict__ el, float* __restrict__ er,
                       const float* __restrict__ lnw, const float* __restrict__ lnb,
                       const double* __restrict__ stat) {
    const int TPS = CO / 2;            // threads per sub-group
    const int SUBS = 256 / TPS;        // 4 (CO=128) or 8 (CO=64)
    const int ROWS = SUBS * 16;        // 64 or 128
    const int BUFSZ = ELR ? (ROWS * 128) : (64 * ROWS);
    size_t m0 = (size_t)blockIdx.x * ROWS;
    int tid = threadIdx.x;
    __shared__ float buf[BUFSZ];
    float* xs = buf;                   // [k][row]
    float* ys = buf;                   // [row][128]  (aliased; used after sync)
    __shared__ float mu_s, rs_s;
    if (LNIN) {
        if (tid == 0) ln_combine(stat, (int)(m0 >> 11), mu_s, rs_s);
        __syncthreads();
    }
    float mu = LNIN ? mu_s : 0.f, rs = LNIN ? rs_s : 1.f;
    for (int i = tid; i < ROWS * 64; i += 256) {
        int r = i >> 6, k = i & 63;
        float v = in[m0 * 64 + i];
        if (LNIN) {
            int n = (int)((m0 + r) & 2047);
            v = (v - mu) * rs * lnw[n * 64 + k] + lnb[n * 64 + k];
        }
        xs[k * ROWS + r] = v;
    }
    __syncthreads();
    int sub = tid / TPS, u = tid % TPS;
    int rbase = sub * 16;
    ull acc_a[8], acc_b[8];
#pragma unroll
    for (int p = 0; p < 8; p++) { acc_a[p] = 0ull; acc_b[p] = 0ull; }
#pragma unroll 8
    for (int k = 0; k < 64; k++) {
        ull wda = dup2(W[k * CO + u]);
        ull wdb = dup2(W[k * CO + u + TPS]);
#pragma unroll
        for (int p = 0; p < 8; p++) {
            ull xv = *(const ull*)&xs[k * ROWS + rbase + 2 * p];
            fma2(acc_a[p], xv, wda);
            fma2(acc_b[p], xv, wdb);
        }
    }
    if (ELR) __syncthreads();  // xs dead; safe to overwrite as ys
    float bva = bias ? bias[u] : 0.f;
    float bvb = bias ? bias[u + TPS] : 0.f;
#pragma unroll
    for (int p = 0; p < 8; p++) {
        float2 va = unpk2(acc_a[p]);
        float2 vb = unpk2(acc_b[p]);
        size_t r0 = m0 + rbase + 2 * p;
        out[r0 * CO + u] = va.x + bva;
        out[(r0 + 1) * CO + u] = va.y + bva;
        out[r0 * CO + u + TPS] = vb.x + bvb;
        out[(r0 + 1) * CO + u + TPS] = vb.y + bvb;
        if (ELR) {
            int rr = rbase + 2 * p;
            ys[rr * 128 + u] = va.x;
            ys[(rr + 1) * 128 + u] = va.y;
            ys[rr * 128 + u + TPS] = vb.x;
            ys[(rr + 1) * 128 + u + TPS] = vb.y;
        }
    }
    if (ELR) {
        __syncthreads();
        // 256 threads -> 128 tasks x 2 halves; task = (r, h)
        int task = tid >> 1, half = tid & 1;
        int r = task >> 1, h = task & 1;
        float sl = 0.f, sr = 0.f;
#pragma unroll
        for (int i = 0; i < 32; i++) {
            int co = h * 64 + half * 32 + i;
            float f = ys[r * 128 + co];
            sl += f * al[co];
            sr += f * ar[co];
        }
        sl += __shfl_xor_sync(0xFFFFFFFFu, sl, 1);
        sr += __shfl_xor_sync(0xFFFFFFFFu, sr, 1);
        if (half == 0) {
            el[(m0 + r) * 2 + h] = sl;
            er[(m0 + r) * 2 + h] = sr;
        }
    }
}

// ---------------- edge softmax alpha ----------------
__global__ void k_alpha(const float* __restrict__ el, const float* __restrict__ er,
                        const int* __restrict__ rowptr, const int* __restrict__ col,
                        float* __restrict__ alpha, int t_in, int Etot) {
    int gw = blockIdx.x * 8 + (threadIdx.x >> 5);
    int n = gw >> 3, b = gw & 7;
    int lane = threadIdx.x & 31;
    int r0 = rowptr[n], deg = rowptr[n + 1] - r0;
    const float2* el2 = (const float2*)el;
    const float2* er2 = (const float2*)er;
    if (deg <= 32) {
        int s = (lane < deg) ? col[r0 + lane] : 0;
        for (int t = 0; t < t_in; t++) {
            int base = (b * t_in + t) * 2048;
            float2 erd = er2[base + n];
            float2 ela = (lane < deg) ? el2[base + s] : make_float2(-3.0e38f, -3.0e38f);
#pragma unroll
            for (int h = 0; h < 2; h++) {
                float v = (h ? ela.y + erd.y : ela.x + erd.x);
                float e = (lane < deg) ? (v > 0.f ? v : 0.2f * v) : -3.0e38f;
                float mx = e;
                for (int o = 16; o; o >>= 1) mx = fmaxf(mx, __shfl_xor_sync(0xFFFFFFFFu, mx, o));
                float a = (lane < deg) ? __expf(e - mx) : 0.f;
                float sm = a;
                for (int o = 16; o; o >>= 1) sm += __shfl_xor_sync(0xFFFFFFFFu, sm, o);
                if (lane < deg)
                    alpha[(size_t)((b * t_in + t) * 2 + h) * Etot + r0 + lane] = a / sm;
            }
        }
    } else {
        for (int t = 0; t < t_in; t++) {
            int base = (b * t_in + t) * 2048;
            for (int h = 0; h < 2; h++) {
                float erd = er[(size_t)(base + n) * 2 + h];
                float mx = -3.0e38f;
                for (int j = lane; j < deg; j += 32) {
                    float v = el[(size_t)(base + col[r0 + j]) * 2 + h] + erd;
                    v = v > 0.f ? v : 0.2f * v;
                    mx = fmaxf(mx, v);
                }
                for (int o = 16; o; o >>= 1) mx = fmaxf(mx, __shfl_xor_sync(0xFFFFFFFFu, mx, o));
                float sm = 0.f;
                for (int j = lane; j < deg; j += 32) {
                    float v = el[(size_t)(base + col[r0 + j]) * 2 + h] + erd;
                    v = v > 0.f ? v : 0.2f * v;
                    sm += __expf(v - mx);
                }
                for (int o = 16; o; o >>= 1) sm += __shfl_xor_sync(0xFFFFFFFFu, sm, o);
                for (int j = lane; j < deg; j += 32) {
                    float v = el[(size_t)(base + col[r0 + j]) * 2 + h] + erd;
                    v = v > 0.f ? v : 0.2f * v;
                    alpha[(size_t)((b * t_in + t) * 2 + h) * Etot + r0 + j] = __expf(v - mx) / sm;
                }
            }
        }
    }
}

// ---------------- gather ----------------
template <int TIN>
__global__ void k_gather(const float* __restrict__ feat, const float* __restrict__ alpha,
                         const int* __restrict__ rowptr, const int* __restrict__ col,
                         const float* __restrict__ bias, float* __restrict__ y, int Etot) {
    int n = blockIdx.x, b = blockIdx.y;
    int c = threadIdx.x;  // 64
    int r0 = rowptr[n], deg = rowptr[n + 1] - r0;
    float acc[TIN * 2];
#pragma unroll
    for (int i = 0; i < TIN * 2; i++) acc[i] = 0.f;
    for (int j = 0; j < deg; j++) {
        int s = col[r0 + j];
#pragma unroll
        for (int t = 0; t < TIN; t++) {
#pragma unroll
            for (int h = 0; h < 2; h++) {
                float a = alpha[(size_t)((b * TIN + t) * 2 + h) * Etot + r0 + j];
                float f = feat[(size_t)((b * TIN + t) * 2048 + s) * 128 + h * 64 + c];
                acc[t * 2 + h] += a * f;
            }
        }
    }
#pragma unroll
    for (int t = 0; t < TIN; t++) {
#pragma unroll
        for (int h = 0; h < 2; h++) {
            float v = acc[t * 2 + h] + bias[h * 64 + c];
            v = v > 0.f ? v : 0.f;
            y[((size_t)(b * 2 * TIN + t * 2 + h) * 2048 + n) * 64 + c] = v;
        }
    }
}

// ---------------- conv1 (K=5) with fused LN input ----------------
__global__ void k_conv1(const float* __restrict__ z, const float* __restrict__ wt1,
                        const float* __restrict__ tb1, float* __restrict__ o1,
                        const float* __restrict__ lnw, const float* __restrict__ lnb,
                        const double* __restrict__ stat) {
    int b = blockIdx.x >> 8;
    int nt = blockIdx.x & 255;
    int n0 = nt * 8;
    __shared__ float zs[16 * 64 * 8];  // [t][ci][nn]
    __shared__ float muv[16], rsv[16];
    if (threadIdx.x < 16)
        ln_combine(stat, b * 16 + threadIdx.x, muv[threadIdx.x], rsv[threadIdx.x]);
    __syncthreads();
    for (int i = threadIdx.x; i < 8192; i += 256) {
        int t = i >> 9;
        int r = i & 511;           // nn*64+ci
        int nn = r >> 6;
        int ci = r & 63;
        float v = z[((size_t)((b * 16 + t) * 2048 + n0)) * 64 + r];
        v = (v - muv[t]) * rsv[t] * lnw[(size_t)n0 * 64 + r] + lnb[(size_t)n0 * 64 + r];
        zs[(t * 64 + ci) * 8 + nn] = v;
    }
    __syncthreads();
    int colc = threadIdx.x & 15;
    int nnp = (threadIdx.x >> 4) & 3;
    int jg = threadIdx.x >> 6;
    ull acc[4][3];
#pragma unroll
    for (int q = 0; q < 4; q++)
#pragma unroll
        for (int jj = 0; jj < 3; jj++) acc[q][jj] = 0ull;
#pragma unroll
    for (int k = 0; k < 5; k++) {
        for (int ci = 0; ci < 64; ci++) {
            float4 w4 = *(const float4*)&wt1[((k * 64 + ci) * 16 + colc) * 4];
            ull w0 = dup2(w4.x), w1 = dup2(w4.y), w2 = dup2(w4.z), w3 = dup2(w4.w);
#pragma unroll
            for (int jj = 0; jj < 3; jj++) {
                int t = jg * 3 + jj + k;
                ull zv = *(const ull*)&zs[(t * 64 + ci) * 8 + nnp * 2];
                fma2(acc[0][jj], zv, w0);
                fma2(acc[1][jj], zv, w1);
                fma2(acc[2][jj], zv, w2);
                fma2(acc[3][jj], zv, w3);
            }
        }
    }
#pragma unroll
    for (int q = 0; q < 4; q++) {
        int co = q * 16 + colc;
        float bv = tb1[co];
#pragma unroll
        for (int jj = 0; jj < 3; jj++) {
            int j = jg * 3 + jj;
            float2 v = unpk2(acc[q][jj]);
            int n = n0 + nnp * 2;
            o1[((size_t)((b * 12 + j) * 2048 + n)) * 64 + co] = v.x + bv;
            o1[((size_t)((b * 12 + j) * 2048 + n + 1)) * 64 + co] = v.y + bv;
        }
    }
}

// ---------------- final FC (scrambled reshape fused) ----------------
__global__ void k_fc(const float* __restrict__ o2, const float* __restrict__ fw,
                     const float* __restrict__ fb, float* __restrict__ out) {
    int b = blockIdx.x >> 5, q = blockIdx.x & 31;
    __shared__ float s[64 * 64];
    int c = threadIdx.x & 63;
    int rb = threadIdx.x >> 6;
    float acc[3] = {0.f, 0.f, 0.f};
    for (int j = 0; j < 12; j++) {
        __syncthreads();
        for (int i = threadIdx.x; i < 4096; i += 256)
            s[i] = o2[((size_t)((b * 12 + j) * 2048 + q * 64)) * 64 + i];
        __syncthreads();
        for (int rn = 0; rn < 64; rn++) {
            float v = s[rn * 64 + c];
#pragma unroll
            for (int rr = 0; rr < 3; rr++)
                acc[rr] += v * fw[(rb * 3 + rr) * 768 + rn * 12 + j];
        }
    }
    int np = 32 * c + q;
#pragma unroll
    for (int rr = 0; rr < 3; rr++) {
        int r = rb * 3 + rr;
        out[((size_t)b * 2048 + np) * 12 + r] = acc[rr] + fb[r];
    }
}

// ---------------- host ----------------
static void* sym(const void* s) {
    void* p = nullptr;
    cudaGetSymbolAddress(&p, s);
    return p;
}

extern "C" void kernel_launch(void* const* d_in, const int* in_sizes, int n_in,
                              void* d_out, int out_size) {
    const float* x = (const float*)d_in[0];
    const int* src = (const int*)d_in[1];
    const int* dst = (const int*)d_in[2];
    const float* W1 = (const float*)d_in[3];
    const float* al1 = (const float*)d_in[4];
    const float* ar1 = (const float*)d_in[5];
    const float* b1 = (const float*)d_in[6];
    const float* W2 = (const float*)d_in[7];
    const float* al2 = (const float*)d_in[8];
    const float* ar2 = (const float*)d_in[9];
    const float* b2 = (const float*)d_in[10];
    const float* ln1w = (const float*)d_in[11];
    const float* ln1b = (const float*)d_in[12];
    const float* ln2w = (const float*)d_in[13];
    const float* ln2b = (const float*)d_in[14];
    const float* tc1w = (const float*)d_in[15];
    const float* tc1b = (const float*)d_in[16];
    const float* ln3w = (const float*)d_in[17];
    const float* ln3b = (const float*)d_in[18];
    const float* tc2w = (const float*)d_in[19];
    const float* tc2b = (const float*)d_in[20];
    const float* fcw = (const float*)d_in[21];
    const float* fcb = (const float*)d_in[22];
    int E = in_sizes[1];

    float* xT = (float*)sym(g_xT);
    float* feat = (float*)sym(g_feat);
    float* el = (float*)sym(g_el);
    float* er = (float*)sym(g_er);
    float* alpha = (float*)sym(g_alpha);
    float* y = (float*)sym(g_y);
    float* z = (float*)sym(g_z);
    float* o1 = (float*)sym(g_o1);
    float* o2 = (float*)sym(g_o2);
    float* wt1 = (float*)sym(g_wt1);
    float* wt2 = (float*)sym(g_wt2);
    double* stat = (double*)sym(g_stat);
    int* deg = (int*)sym(g_deg);
    int* rowptr = (int*)sym(g_rowptr);
    int* col = (int*)sym(g_col);
    float* out = (float*)d_out;

    // launches 1-4 (setup), so launch #5 (ncu capture) = gemm1
    k_transpose_x<<<16384, 256>>>(x, xT, deg);
    k_count<<<(E + 255) / 256, 256>>>(dst, deg, E);
    k_scan<<<1, 1024>>>(deg, rowptr);
    k_fill<<<256, 256>>>(dst, src, rowptr, col, E);

    // ---- GAT layer 1 ----
    k_gemm<128, true, false><<<1024, 256>>>(xT, W1, nullptr, feat, al1, ar1, el, er,
                                            nullptr, nullptr, nullptr);
    k_alpha<<<2048, 256>>>(el, er, rowptr, col, alpha, 4, E);
    {
        dim3 g(2048, 8);
        k_gather<4><<<g, 64>>>(feat, alpha, rowptr, col, b1, y, E);
    }
    k_lnpart<<<256, 1024>>>(y, stat);  // 64 slices x 4

    // ---- GAT layer 2 (LN1 fused into GEMM input) ----
    k_gemm<128, true, true><<<2048, 256>>>(y, W2, nullptr, feat, al2, ar2, el, er,
                                           ln1w, ln1b, stat);
    k_alpha<<<2048, 256>>>(el, er, rowptr, col, alpha, 8, E);
    {
        dim3 g(2048, 8);
        k_gather<8><<<g, 64>>>(feat, alpha, rowptr, col, b2, z, E);
    }
    k_lnpart<<<512, 1024>>>(z, stat);  // 128 slices x 4

    // ---- output layer ----
    k_tw1<<<80, 256>>>(tc1w, wt1);
    k_tw2<<<16, 256>>>(tc2w, wt2);
    k_conv1<<<2048, 256>>>(z, wt1, tc1b, o1, ln2w, ln2b, stat);  // LN2 fused
    k_lnpart<<<384, 1024>>>(o1, stat);  // 96 slices x 4
    k_gemm<64, false, true><<<1536, 256>>>(o1, wt2, tc2b, o2, nullptr, nullptr, nullptr,
                                           nullptr, ln3w, ln3b, stat);  // LN3 fused
    k_fc<<<256, 256>>>(o2, fcw, fcb, out);
}

// round 7
// speedup vs baseline: 1.5163x; 1.0745x over previous
#include <cuda_runtime.h>
#include <cuda_bf16.h>
#include <math.h>

#define NN_ 2048
#define BB_ 8

typedef unsigned long long ull;

__device__ __forceinline__ ull pk2(float x, float y) {
    ull r; asm("mov.b64 %0,{%1,%2};" : "=l"(r) : "f"(x), "f"(y)); return r;
}
__device__ __forceinline__ ull dup2(float x) { return pk2(x, x); }
__device__ __forceinline__ void fma2(ull& d, ull a, ull b) {
    asm("fma.rn.f32x2 %0,%1,%2,%0;" : "+l"(d) : "l"(a), "l"(b));
}
__device__ __forceinline__ float2 unpk2(ull v) {
    float2 f; asm("mov.b64 {%0,%1},%2;" : "=f"(f.x), "=f"(f.y) : "l"(v)); return f;
}

// ---------------- scratch ----------------
__device__ float g_xT[4194304];      // [B,4,N,C]
__device__ float g_feat[16777216];   // node-major [n][b][t][128]
__device__ float g_el[262144];       // [b,t,n,2]
__device__ float g_er[262144];
__device__ float g_alpha[1310720];   // [e][b][2*TIN]  (E_max=10240 * 8 * 16)
__device__ float g_y[16777216];      // [b,8,n,64]
__device__ float g_z[16777216];      // [b,16,n,64]
__device__ float g_o1[12582912];     // [b,12,n,64]
__device__ float g_o2[12582912];
__device__ float g_wt1[20480];       // [k][ci][col16][q4]
__device__ float g_wt2[4096];        // [ci][co]
__device__ double g_stat[1024];
__device__ int   g_deg[2048];
__device__ int   g_cursor[2048];
__device__ int   g_rowptr[2049];
__device__ int   g_col[16384];

// ---------------- transpose x (+ zero deg) ----------------
__global__ void k_transpose_x(const float* __restrict__ x, float* __restrict__ xT,
                              int* __restrict__ deg) {
    int i = blockIdx.x * 256 + threadIdx.x;
    if (i < 2048) deg[i] = 0;
    if (i >= BB_ * NN_ * 4 * 64) return;
    int c = i & 63;
    int t = (i >> 6) & 3;
    int n = (i >> 8) & 2047;
    int b = i >> 19;
    xT[((size_t)(b * 4 + t) * 2048 + n) * 64 + c] = x[i];
}

// ---------------- CSR build ----------------
__global__ void k_count(const int* __restrict__ dst, int* __restrict__ deg, int E) {
    int e = blockIdx.x * 256 + threadIdx.x;
    if (e < E) atomicAdd(&deg[dst[e]], 1);
}

__global__ void k_scan(const int* __restrict__ deg, int* __restrict__ rowptr,
                       int* __restrict__ cursor) {
    __shared__ int s[2048];
    int tid = threadIdx.x;
    s[tid] = deg[tid];
    s[tid + 1024] = deg[tid + 1024];
    __syncthreads();
    for (int off = 1; off < 2048; off <<= 1) {
        int i0 = tid, i1 = tid + 1024;
        int a0 = (i0 >= off) ? s[i0 - off] : 0;
        int a1 = (i1 >= off) ? s[i1 - off] : 0;
        __syncthreads();
        s[i0] += a0; s[i1] += a1;
        __syncthreads();
    }
    rowptr[tid + 1] = s[tid];
    rowptr[tid + 1025] = s[tid + 1024];
    if (tid == 0) { rowptr[0] = 0; cursor[0] = 0; }
    if (tid < 1023) cursor[tid + 1] = s[tid];
    cursor[tid + 1024] = s[tid + 1023];
}

// atomic scatter fill (order fixed up by sort)
__global__ void k_fill_atomic(const int* __restrict__ dst, const int* __restrict__ src,
                              int* __restrict__ cursor, int* __restrict__ col, int E) {
    int e = blockIdx.x * 256 + threadIdx.x;
    if (e >= E) return;
    int pos = atomicAdd(&cursor[dst[e]], 1);
    col[pos] = src[e];
}

// canonical per-node sort (insertion; deg is small) -> deterministic order
__global__ void k_sortcol(const int* __restrict__ rowptr, int* __restrict__ col) {
    int n = blockIdx.x * 256 + threadIdx.x;
    if (n >= NN_) return;
    int r0 = rowptr[n], r1 = rowptr[n + 1];
    for (int i = r0 + 1; i < r1; i++) {
        int v = col[i];
        int j = i - 1;
        while (j >= r0 && col[j] > v) { col[j + 1] = col[j]; j--; }
        col[j + 1] = v;
    }
}

// ---------------- weight transposes ----------------
__global__ void k_tw1(const float* __restrict__ w, float* __restrict__ wt) {
    int i = blockIdx.x * 256 + threadIdx.x;
    if (i >= 20480) return;
    int q = i & 3;
    int colc = (i >> 2) & 15;
    int ci = (i >> 6) & 63;
    int k = i >> 12;
    int co = q * 16 + colc;
    wt[i] = w[(co * 64 + ci) * 5 + k];
}

__global__ void k_tw2(const float* __restrict__ w, float* __restrict__ wt) {
    int i = blockIdx.x * 256 + threadIdx.x;
    if (i >= 4096) return;
    int ci = i >> 6, co = i & 63;
    wt[i] = w[co * 64 + ci];
}

// ---------------- LN partial stats ----------------
__global__ void k_lnpart(const float* __restrict__ x, double* __restrict__ stat) {
    int slice = blockIdx.x >> 2, q = blockIdx.x & 3;
    const float* xs = x + (size_t)slice * 131072 + q * 32768;
    double s1 = 0.0, s2 = 0.0;
    for (int i = threadIdx.x; i < 32768; i += 1024) {
        float v = xs[i];
        s1 += v;
        s2 += (double)v * (double)v;
    }
    for (int o = 16; o; o >>= 1) {
        s1 += __shfl_xor_sync(0xFFFFFFFFu, s1, o);
        s2 += __shfl_xor_sync(0xFFFFFFFFu, s2, o);
    }
    __shared__ double sh1[32], sh2[32];
    int wid = threadIdx.x >> 5, lane = threadIdx.x & 31;
    if (!lane) { sh1[wid] = s1; sh2[wid] = s2; }
    __syncthreads();
    if (threadIdx.x == 0) {
        double t1 = 0, t2 = 0;
        for (int k = 0; k < 32; k++) { t1 += sh1[k]; t2 += sh2[k]; }
        stat[slice * 8 + q * 2] = t1;
        stat[slice * 8 + q * 2 + 1] = t2;
    }
}

__device__ __forceinline__ void ln_combine(const double* __restrict__ stat, int slice,
                                           float& mu, float& rs) {
    double t1 = 0, t2 = 0;
#pragma unroll
    for (int q = 0; q < 4; q++) {
        t1 += stat[slice * 8 + q * 2];
        t2 += stat[slice * 8 + q * 2 + 1];
    }
    double m = t1 / 131072.0;
    double var = t2 / 131072.0 - m * m;
    mu = (float)m;
    rs = (float)rsqrt(var + 1e-5);
}

// ---------------- GEMM: f32x2, 2 co/thread; ELR -> feat node-major + el/er ----------------
template <int CO, bool ELR, bool LNIN, int TIN>
__global__ void k_gemm(const float* __restrict__ in, const float* __restrict__ W,
                       const float* __restrict__ bias, float* __restrict__ out,
                       const float* __restrict__ al, const float* __restrict__ ar,
                       float* __restrict__ el, float* __restrict__ er,
                       const float* __restrict__ lnw, const float* __restrict__ lnb,
                       const double* __restrict__ stat) {
    const int TPS = CO / 2;
    const int SUBS = 256 / TPS;
    const int ROWS = SUBS * 16;        // 64 (CO=128) or 128 (CO=64)
    const int BUFSZ = ELR ? (ROWS * 128) : (64 * ROWS);
    size_t m0 = (size_t)blockIdx.x * ROWS;
    int tid = threadIdx.x;
    __shared__ float buf[BUFSZ];
    float* xs = buf;                   // [k][row]
    float* ys = buf;                   // [row][128] (aliased, post-sync)
    __shared__ float mu_s, rs_s;
    if (LNIN) {
        if (tid == 0) ln_combine(stat, (int)(m0 >> 11), mu_s, rs_s);
        __syncthreads();
    }
    float mu = LNIN ? mu_s : 0.f, rs = LNIN ? rs_s : 1.f;
    for (int i = tid; i < ROWS * 64; i += 256) {
        int r = i >> 6, k = i & 63;
        float v = in[m0 * 64 + i];
        if (LNIN) {
            int n = (int)((m0 + r) & 2047);
            v = (v - mu) * rs * lnw[n * 64 + k] + lnb[n * 64 + k];
        }
        xs[k * ROWS + r] = v;
    }
    __syncthreads();
    int sub = tid / TPS, u = tid % TPS;
    int rbase = sub * 16;
    ull acc_a[8], acc_b[8];
#pragma unroll
    for (int p = 0; p < 8; p++) { acc_a[p] = 0ull; acc_b[p] = 0ull; }
#pragma unroll 8
    for (int k = 0; k < 64; k++) {
        ull wda = dup2(W[k * CO + u]);
        ull wdb = dup2(W[k * CO + u + TPS]);
#pragma unroll
        for (int p = 0; p < 8; p++) {
            ull xv = *(const ull*)&xs[k * ROWS + rbase + 2 * p];
            fma2(acc_a[p], xv, wda);
            fma2(acc_b[p], xv, wdb);
        }
    }
    if (ELR) {
        __syncthreads();  // xs dead; reuse as ys
        // feat node-major base: n = m&2047, bt = m>>11 (= b*TIN+t)
        const size_t rowstride = (size_t)8 * TIN * 128;
        size_t fbase = (size_t)(m0 & 2047) * rowstride + (size_t)(m0 >> 11) * 128;
#pragma unroll
        for (int p = 0; p < 8; p++) {
            float2 va = unpk2(acc_a[p]);
            float2 vb = unpk2(acc_b[p]);
            int rr = rbase + 2 * p;
            out[fbase + (size_t)rr * rowstride + u] = va.x;
            out[fbase + (size_t)(rr + 1) * rowstride + u] = va.y;
            out[fbase + (size_t)rr * rowstride + u + TPS] = vb.x;
            out[fbase + (size_t)(rr + 1) * rowstride + u + TPS] = vb.y;
            ys[rr * 128 + u] = va.x;
            ys[(rr + 1) * 128 + u] = va.y;
            ys[rr * 128 + u + TPS] = vb.x;
            ys[(rr + 1) * 128 + u + TPS] = vb.y;
        }
        __syncthreads();
        int task = tid >> 1, half = tid & 1;
        int r = task >> 1, h = task & 1;
        float sl = 0.f, sr = 0.f;
#pragma unroll
        for (int i = 0; i < 32; i++) {
            int co = h * 64 + half * 32 + i;
            float f = ys[r * 128 + co];
            sl += f * al[co];
            sr += f * ar[co];
        }
        sl += __shfl_xor_sync(0xFFFFFFFFu, sl, 1);
        sr += __shfl_xor_sync(0xFFFFFFFFu, sr, 1);
        if (half == 0) {
            el[(m0 + r) * 2 + h] = sl;
            er[(m0 + r) * 2 + h] = sr;
        }
    } else {
        float bva = bias ? bias[u] : 0.f;
        float bvb = bias ? bias[u + TPS] : 0.f;
#pragma unroll
        for (int p = 0; p < 8; p++) {
            float2 va = unpk2(acc_a[p]);
            float2 vb = unpk2(acc_b[p]);
            size_t r0 = m0 + rbase + 2 * p;
            out[r0 * CO + u] = va.x + bva;
            out[(r0 + 1) * CO + u] = va.y + bva;
            out[r0 * CO + u + TPS] = vb.x + bvb;
            out[(r0 + 1) * CO + u + TPS] = vb.y + bvb;
        }
    }
}

// ---------------- edge softmax alpha: [e][b][2*TIN] ----------------
template <int TIN>
__global__ void k_alpha(const float* __restrict__ el, const float* __restrict__ er,
                        const int* __restrict__ rowptr, const int* __restrict__ col,
                        float* __restrict__ alpha) {
    const int STR = 2 * TIN;
    int gw = blockIdx.x * 8 + (threadIdx.x >> 5);
    int n = gw >> 3, b = gw & 7;
    int lane = threadIdx.x & 31;
    int r0 = rowptr[n], deg = rowptr[n + 1] - r0;
    const float2* el2 = (const float2*)el;
    const float2* er2 = (const float2*)er;
    if (deg <= 32) {
        int s = (lane < deg) ? col[r0 + lane] : 0;
        float av[STR];
        for (int t = 0; t < TIN; t++) {
            int base = (b * TIN + t) * 2048;
            float2 erd = er2[base + n];
            float2 ela = (lane < deg) ? el2[base + s] : make_float2(-3.0e38f, -3.0e38f);
#pragma unroll
            for (int h = 0; h < 2; h++) {
                float v = (h ? ela.y + erd.y : ela.x + erd.x);
                float e = (lane < deg) ? (v > 0.f ? v : 0.2f * v) : -3.0e38f;
                float mx = e;
                for (int o = 16; o; o >>= 1) mx = fmaxf(mx, __shfl_xor_sync(0xFFFFFFFFu, mx, o));
                float a = (lane < deg) ? __expf(e - mx) : 0.f;
                float sm = a;
                for (int o = 16; o; o >>= 1) sm += __shfl_xor_sync(0xFFFFFFFFu, sm, o);
                av[t * 2 + h] = a / sm;
            }
        }
        if (lane < deg) {
            float4* ap = (float4*)&alpha[((size_t)(r0 + lane) * 8 + b) * STR];
#pragma unroll
            for (int q = 0; q < STR / 4; q++) ap[q] = ((float4*)av)[q];
        }
    } else {
        for (int t = 0; t < TIN; t++) {
            int base = (b * TIN + t) * 2048;
            for (int h = 0; h < 2; h++) {
                float erd = er[(size_t)(base + n) * 2 + h];
                float mx = -3.0e38f;
                for (int j = lane; j < deg; j += 32) {
                    float v = el[(size_t)(base + col[r0 + j]) * 2 + h] + erd;
                    v = v > 0.f ? v : 0.2f * v;
                    mx = fmaxf(mx, v);
                }
                for (int o = 16; o; o >>= 1) mx = fmaxf(mx, __shfl_xor_sync(0xFFFFFFFFu, mx, o));
                float sm = 0.f;
                for (int j = lane; j < deg; j += 32) {
                    float v = el[(size_t)(base + col[r0 + j]) * 2 + h] + erd;
                    v = v > 0.f ? v : 0.2f * v;
                    sm += __expf(v - mx);
                }
                for (int o = 16; o; o >>= 1) sm += __shfl_xor_sync(0xFFFFFFFFu, sm, o);
                for (int j = lane; j < deg; j += 32) {
                    float v = el[(size_t)(base + col[r0 + j]) * 2 + h] + erd;
                    v = v > 0.f ? v : 0.2f * v;
                    alpha[((size_t)(r0 + j) * 8 + b) * STR + t * 2 + h] = __expf(v - mx) / sm;
                }
            }
        }
    }
}

// ---------------- gather: node-major feat, alpha [e][b][STR] ----------------
template <int TIN>
__global__ void k_gather(const float* __restrict__ feat, const float* __restrict__ alpha,
                         const int* __restrict__ rowptr, const int* __restrict__ col,
                         const float* __restrict__ bias, float* __restrict__ y) {
    const int STR = 2 * TIN;
    int n = blockIdx.x, b = blockIdx.y;
    int c = threadIdx.x;  // 64
    int r0 = rowptr[n], deg = rowptr[n + 1] - r0;
    float acc[STR];
#pragma unroll
    for (int i = 0; i < STR; i++) acc[i] = 0.f;
    for (int j = 0; j < deg; j++) {
        int s = col[r0 + j];
        float av[STR];
        const float4* ap = (const float4*)&alpha[((size_t)(r0 + j) * 8 + b) * STR];
#pragma unroll
        for (int q = 0; q < STR / 4; q++) ((float4*)av)[q] = ap[q];  // broadcast
        const float* fp = feat + ((size_t)s * 8 + b) * (TIN * 128) + c;
#pragma unroll
        for (int t = 0; t < TIN; t++) {
#pragma unroll
            for (int h = 0; h < 2; h++)
                acc[t * 2 + h] += av[t * 2 + h] * fp[t * 128 + h * 64];
        }
    }
#pragma unroll
    for (int t = 0; t < TIN; t++) {
#pragma unroll
        for (int h = 0; h < 2; h++) {
            float v = acc[t * 2 + h] + bias[h * 64 + c];
            v = v > 0.f ? v : 0.f;
            y[((size_t)(b * 2 * TIN + t * 2 + h) * 2048 + n) * 64 + c] = v;
        }
    }
}

// ---------------- conv1 (K=5) with fused LN input ----------------
__global__ void k_conv1(const float* __restrict__ z, const float* __restrict__ wt1,
                        const float* __restrict__ tb1, float* __restrict__ o1,
                        const float* __restrict__ lnw, const float* __restrict__ lnb,
                        const double* __restrict__ stat) {
    int b = blockIdx.x >> 8;
    int nt = blockIdx.x & 255;
    int n0 = nt * 8;
    __shared__ float zs[16 * 64 * 8];  // [t][ci][nn]
    __shared__ float muv[16], rsv[16];
    if (threadIdx.x < 16)
        ln_combine(stat, b * 16 + threadIdx.x, muv[threadIdx.x], rsv[threadIdx.x]);
    __syncthreads();
    for (int i = threadIdx.x; i < 8192; i += 256) {
        int t = i >> 9;
        int r = i & 511;
        int nn = r >> 6;
        int ci = r & 63;
        float v = z[((size_t)((b * 16 + t) * 2048 + n0)) * 64 + r];
        v = (v - muv[t]) * rsv[t] * lnw[(size_t)n0 * 64 + r] + lnb[(size_t)n0 * 64 + r];
        zs[(t * 64 + ci) * 8 + nn] = v;
    }
    __syncthreads();
    int colc = threadIdx.x & 15;
    int nnp = (threadIdx.x >> 4) & 3;
    int jg = threadIdx.x >> 6;
    ull acc[4][3];
#pragma unroll
    for (int q = 0; q < 4; q++)
#pragma unroll
        for (int jj = 0; jj < 3; jj++) acc[q][jj] = 0ull;
#pragma unroll
    for (int k = 0; k < 5; k++) {
        for (int ci = 0; ci < 64; ci++) {
            float4 w4 = *(const float4*)&wt1[((k * 64 + ci) * 16 + colc) * 4];
            ull w0 = dup2(w4.x), w1 = dup2(w4.y), w2 = dup2(w4.z), w3 = dup2(w4.w);
#pragma unroll
            for (int jj = 0; jj < 3; jj++) {
                int t = jg * 3 + jj + k;
                ull zv = *(const ull*)&zs[(t * 64 + ci) * 8 + nnp * 2];
                fma2(acc[0][jj], zv, w0);
                fma2(acc[1][jj], zv, w1);
                fma2(acc[2][jj], zv, w2);
                fma2(acc[3][jj], zv, w3);
            }
        }
    }
#pragma unroll
    for (int q = 0; q < 4; q++) {
        int co = q * 16 + colc;
        float bv = tb1[co];
#pragma unroll
        for (int jj = 0; jj < 3; jj++) {
            int j = jg * 3 + jj;
            float2 v = unpk2(acc[q][jj]);
            int n = n0 + nnp * 2;
            o1[((size_t)((b * 12 + j) * 2048 + n)) * 64 + co] = v.x + bv;
            o1[((size_t)((b * 12 + j) * 2048 + n + 1)) * 64 + co] = v.y + bv;
        }
    }
}

// ---------------- final FC (scrambled reshape fused) ----------------
__global__ void k_fc(const float* __restrict__ o2, const float* __restrict__ fw,
                     const float* __restrict__ fb, float* __restrict__ out) {
    int b = blockIdx.x >> 5, q = blockIdx.x & 31;
    __shared__ float s[64 * 64];
    int c = threadIdx.x & 63;
    int rb = threadIdx.x >> 6;
    float acc[3] = {0.f, 0.f, 0.f};
    for (int j = 0; j < 12; j++) {
        __syncthreads();
        for (int i = threadIdx.x; i < 4096; i += 256)
            s[i] = o2[((size_t)((b * 12 + j) * 2048 + q * 64)) * 64 + i];
        __syncthreads();
        for (int rn = 0; rn < 64; rn++) {
            float v = s[rn * 64 + c];
#pragma unroll
            for (int rr = 0; rr < 3; rr++)
                acc[rr] += v * fw[(rb * 3 + rr) * 768 + rn * 12 + j];
        }
    }
    int np = 32 * c + q;
#pragma unroll
    for (int rr = 0; rr < 3; rr++) {
        int r = rb * 3 + rr;
        out[((size_t)b * 2048 + np) * 12 + r] = acc[rr] + fb[r];
    }
}

// ---------------- host ----------------
static void* sym(const void* s) {
    void* p = nullptr;
    cudaGetSymbolAddress(&p, s);
    return p;
}

extern "C" void kernel_launch(void* const* d_in, const int* in_sizes, int n_in,
                              void* d_out, int out_size) {
    const float* x = (const float*)d_in[0];
    const int* src = (const int*)d_in[1];
    const int* dst = (const int*)d_in[2];
    const float* W1 = (const float*)d_in[3];
    const float* al1 = (const float*)d_in[4];
    const float* ar1 = (const float*)d_in[5];
    const float* b1 = (const float*)d_in[6];
    const float* W2 = (const float*)d_in[7];
    const float* al2 = (const float*)d_in[8];
    const float* ar2 = (const float*)d_in[9];
    const float* b2 = (const float*)d_in[10];
    const float* ln1w = (const float*)d_in[11];
    const float* ln1b = (const float*)d_in[12];
    const float* ln2w = (const float*)d_in[13];
    const float* ln2b = (const float*)d_in[14];
    const float* tc1w = (const float*)d_in[15];
    const float* tc1b = (const float*)d_in[16];
    const float* ln3w = (const float*)d_in[17];
    const float* ln3b = (const float*)d_in[18];
    const float* tc2w = (const float*)d_in[19];
    const float* tc2b = (const float*)d_in[20];
    const float* fcw = (const float*)d_in[21];
    const float* fcb = (const float*)d_in[22];
    int E = in_sizes[1];

    float* xT = (float*)sym(g_xT);
    float* feat = (float*)sym(g_feat);
    float* el = (float*)sym(g_el);
    float* er = (float*)sym(g_er);
    float* alpha = (float*)sym(g_alpha);
    float* y = (float*)sym(g_y);
    float* z = (float*)sym(g_z);
    float* o1 = (float*)sym(g_o1);
    float* o2 = (float*)sym(g_o2);
    float* wt1 = (float*)sym(g_wt1);
    float* wt2 = (float*)sym(g_wt2);
    double* stat = (double*)sym(g_stat);
    int* deg = (int*)sym(g_deg);
    int* cursor = (int*)sym(g_cursor);
    int* rowptr = (int*)sym(g_rowptr);
    int* col = (int*)sym(g_col);
    float* out = (float*)d_out;

    // kernel launches 1-3 (setup) so capture slot #4 = gemm1
    k_transpose_x<<<16384, 256>>>(x, xT, deg);                        // 1
    k_count<<<(E + 255) / 256, 256>>>(dst, deg, E);                   // 2
    k_scan<<<1, 1024>>>(deg, rowptr, cursor);                         // 3
    k_gemm<128, true, false, 4><<<1024, 256>>>(xT, W1, nullptr, feat, // 4  <- ncu capture
                                               al1, ar1, el, er, nullptr, nullptr, nullptr);
    k_fill_atomic<<<(E + 255) / 256, 256>>>(dst, src, cursor, col, E);// 5
    k_sortcol<<<8, 256>>>(rowptr, col);                               // 6

    // ---- GAT layer 1 ----
    k_alpha<4><<<2048, 256>>>(el, er, rowptr, col, alpha);
    {
        dim3 g(2048, 8);
        k_gather<4><<<g, 64>>>(feat, alpha, rowptr, col, b1, y);
    }
    k_lnpart<<<256, 1024>>>(y, stat);

    // ---- GAT layer 2 (LN1 fused into GEMM input) ----
    k_gemm<128, true, true, 8><<<2048, 256>>>(y, W2, nullptr, feat, al2, ar2, el, er,
                                              ln1w, ln1b, stat);
    k_alpha<8><<<2048, 256>>>(el, er, rowptr, col, alpha);
    {
        dim3 g(2048, 8);
        k_gather<8><<<g, 64>>>(feat, alpha, rowptr, col, b2, z);
    }
    k_lnpart<<<512, 1024>>>(z, stat);

    // ---- output layer ----
    k_tw1<<<80, 256>>>(tc1w, wt1);
    k_tw2<<<16, 256>>>(tc2w, wt2);
    k_conv1<<<2048, 256>>>(z, wt1, tc1b, o1, ln2w, ln2b, stat);  // LN2 fused
    k_lnpart<<<384, 1024>>>(o1, stat);
    k_gemm<64, false, true, 0><<<1536, 256>>>(o1, wt2, tc2b, o2, nullptr, nullptr, nullptr,
                                              nullptr, ln3w, ln3b, stat);  // LN3 fused
    k_fc<<<256, 256>>>(o2, fcw, fcb, out);
}

// round 8
// speedup vs baseline: 1.5834x; 1.0442x over previous
#include <cuda_runtime.h>
#include <cuda_bf16.h>
#include <math.h>

#define NN_ 2048
#define BB_ 8

typedef unsigned long long ull;

__device__ __forceinline__ ull pk2(float x, float y) {
    ull r; asm("mov.b64 %0,{%1,%2};" : "=l"(r) : "f"(x), "f"(y)); return r;
}
__device__ __forceinline__ ull dup2(float x) { return pk2(x, x); }
__device__ __forceinline__ void fma2(ull& d, ull a, ull b) {
    asm("fma.rn.f32x2 %0,%1,%2,%0;" : "+l"(d) : "l"(a), "l"(b));
}
__device__ __forceinline__ float2 unpk2(ull v) {
    float2 f; asm("mov.b64 {%0,%1},%2;" : "=f"(f.x), "=f"(f.y) : "l"(v)); return f;
}
__device__ __forceinline__ void lds128(ull& a, ull& b, const float* p) {
    unsigned addr = (unsigned)__cvta_generic_to_shared((void*)p);
    asm("ld.shared.v2.b64 {%0,%1},[%2];" : "=l"(a), "=l"(b) : "r"(addr));
}
__device__ __forceinline__ float wred(float v) {
#pragma unroll
    for (int o = 16; o; o >>= 1) v += __shfl_xor_sync(0xFFFFFFFFu, v, o);
    return v;
}

// ---------------- scratch ----------------
__device__ float g_xT[4194304];      // [B,4,N,C]
__device__ float g_feat[16777216];   // node-major [n][b][t][128]
__device__ float g_el[262144];       // [b,t,n,2]
__device__ float g_er[262144];
__device__ float g_alpha[1310720];   // [e][b][2*TIN]
__device__ float g_y[16777216];      // [b,8,n,64]
__device__ float g_z[16777216];      // [b,16,n,64]
__device__ float g_o1[12582912];     // [b,12,n,64]
__device__ float g_o2[12582912];
__device__ float g_wt1[20480];       // conv1 weights [k][ci][col16][q4]
__device__ float g_wp1[8192];        // W1 packed [k][lane32][4]
__device__ float g_wp2[8192];        // W2 packed [k][lane32][4]
__device__ float g_wpt2[4096];       // tc2 packed [k=ci][lane32][2]
__device__ double g_stat[1024];
__device__ int   g_deg[2048];
__device__ int   g_cursor[2048];
__device__ int   g_rowptr[2049];
__device__ int   g_col[16384];

// ---------------- transpose x (+ zero deg) ----------------
__global__ void k_transpose_x(const float* __restrict__ x, float* __restrict__ xT,
                              int* __restrict__ deg) {
    int i = blockIdx.x * 256 + threadIdx.x;
    if (i < 2048) deg[i] = 0;
    if (i >= BB_ * NN_ * 4 * 64) return;
    int c = i & 63;
    int t = (i >> 6) & 3;
    int n = (i >> 8) & 2047;
    int b = i >> 19;
    xT[((size_t)(b * 4 + t) * 2048 + n) * 64 + c] = x[i];
}

// ---------------- CSR build ----------------
__global__ void k_count(const int* __restrict__ dst, int* __restrict__ deg, int E) {
    int e = blockIdx.x * 256 + threadIdx.x;
    if (e < E) atomicAdd(&deg[dst[e]], 1);
}

__global__ void k_scan(const int* __restrict__ deg, int* __restrict__ rowptr,
                       int* __restrict__ cursor) {
    __shared__ int s[2048];
    int tid = threadIdx.x;
    s[tid] = deg[tid];
    s[tid + 1024] = deg[tid + 1024];
    __syncthreads();
    for (int off = 1; off < 2048; off <<= 1) {
        int i0 = tid, i1 = tid + 1024;
        int a0 = (i0 >= off) ? s[i0 - off] : 0;
        int a1 = (i1 >= off) ? s[i1 - off] : 0;
        __syncthreads();
        s[i0] += a0; s[i1] += a1;
        __syncthreads();
    }
    rowptr[tid + 1] = s[tid];
    rowptr[tid + 1025] = s[tid + 1024];
    if (tid == 0) { rowptr[0] = 0; cursor[0] = 0; }
    if (tid < 1023) cursor[tid + 1] = s[tid];
    cursor[tid + 1024] = s[tid + 1023];
}

__global__ void k_fill_atomic(const int* __restrict__ dst, const int* __restrict__ src,
                              int* __restrict__ cursor, int* __restrict__ col, int E) {
    int e = blockIdx.x * 256 + threadIdx.x;
    if (e >= E) return;
    int pos = atomicAdd(&cursor[dst[e]], 1);
    col[pos] = src[e];
}

__global__ void k_sortcol(const int* __restrict__ rowptr, int* __restrict__ col) {
    int n = blockIdx.x * 256 + threadIdx.x;
    if (n >= NN_) return;
    int r0 = rowptr[n], r1 = rowptr[n + 1];
    for (int i = r0 + 1; i < r1; i++) {
        int v = col[i];
        int j = i - 1;
        while (j >= r0 && col[j] > v) { col[j + 1] = col[j]; j--; }
        col[j + 1] = v;
    }
}

// ---------------- weight prep ----------------
__global__ void k_tw1(const float* __restrict__ w, float* __restrict__ wt) {
    int i = blockIdx.x * 256 + threadIdx.x;
    if (i >= 20480) return;
    int q = i & 3;
    int colc = (i >> 2) & 15;
    int ci = (i >> 6) & 63;
    int k = i >> 12;
    int co = q * 16 + colc;
    wt[i] = w[(co * 64 + ci) * 5 + k];
}

// W [64 k][128 co] -> wp [(k*32+lane)*4 + j] = W[k*128 + lane + 32*j]
__global__ void k_packw128(const float* __restrict__ w, float* __restrict__ wp) {
    int i = blockIdx.x * 256 + threadIdx.x;
    if (i >= 8192) return;
    int k = i >> 7, rem = i & 127, j = rem >> 5, lane = rem & 31;
    wp[(k * 32 + lane) * 4 + j] = w[i];
}

// tc2w [co][ci] -> wp [(ci*32+lane)*2 + j] = w[(lane+32j)*64 + ci]
__global__ void k_packw64(const float* __restrict__ w, float* __restrict__ wp) {
    int i = blockIdx.x * 256 + threadIdx.x;
    if (i >= 4096) return;
    int ci = i >> 6, rem = i & 63, j = rem >> 5, lane = rem & 31;
    wp[(ci * 32 + lane) * 2 + j] = w[(lane + 32 * j) * 64 + ci];
}

// ---------------- LN partial stats ----------------
__global__ void k_lnpart(const float* __restrict__ x, double* __restrict__ stat) {
    int slice = blockIdx.x >> 2, q = blockIdx.x & 3;
    const float* xs = x + (size_t)slice * 131072 + q * 32768;
    double s1 = 0.0, s2 = 0.0;
    for (int i = threadIdx.x; i < 32768; i += 1024) {
        float v = xs[i];
        s1 += v;
        s2 += (double)v * (double)v;
    }
    for (int o = 16; o; o >>= 1) {
        s1 += __shfl_xor_sync(0xFFFFFFFFu, s1, o);
        s2 += __shfl_xor_sync(0xFFFFFFFFu, s2, o);
    }
    __shared__ double sh1[32], sh2[32];
    int wid = threadIdx.x >> 5, lane = threadIdx.x & 31;
    if (!lane) { sh1[wid] = s1; sh2[wid] = s2; }
    __syncthreads();
    if (threadIdx.x == 0) {
        double t1 = 0, t2 = 0;
        for (int k = 0; k < 32; k++) { t1 += sh1[k]; t2 += sh2[k]; }
        stat[slice * 8 + q * 2] = t1;
        stat[slice * 8 + q * 2 + 1] = t2;
    }
}

__device__ __forceinline__ void ln_combine(const double* __restrict__ stat, int slice,
                                           float& mu, float& rs) {
    double t1 = 0, t2 = 0;
#pragma unroll
    for (int q = 0; q < 4; q++) {
        t1 += stat[slice * 8 + q * 2];
        t2 += stat[slice * 8 + q * 2 + 1];
    }
    double m = t1 / 131072.0;
    double var = t2 / 131072.0 - m * m;
    mu = (float)m;
    rs = (float)rsqrt(var + 1e-5);
}

// ---------------- warp-tiled GEMM: 16 rows x CO per warp, f32x2 ----------------
// CO=128: 4 cols/thread; CO=64: 2 cols/thread. ROWS=128 per block (8 warps).
template <int CO, bool ELR, bool LNIN, int TIN>
__global__ __launch_bounds__(256) void k_gemm(
        const float* __restrict__ in, const float* __restrict__ wp,
        const float* __restrict__ bias, float* __restrict__ out,
        const float* __restrict__ al, const float* __restrict__ ar,
        float* __restrict__ el, float* __restrict__ er,
        const float* __restrict__ lnw, const float* __restrict__ lnb,
        const double* __restrict__ stat) {
    const int CPT = CO / 32;           // 4 or 2
    size_t m0 = (size_t)blockIdx.x * 128;
    int tid = threadIdx.x;
    int warp = tid >> 5, lane = tid & 31;
    __shared__ __align__(16) float xs[64 * 128];   // [k][row]
    __shared__ float mu_s, rs_s;
    if (LNIN) {
        if (tid == 0) ln_combine(stat, (int)(m0 >> 11), mu_s, rs_s);
        __syncthreads();
    }
    float mu = LNIN ? mu_s : 0.f, rs = LNIN ? rs_s : 1.f;
    for (int i = tid; i < 128 * 64; i += 256) {
        int r = i >> 6, k = i & 63;
        float v = in[m0 * 64 + i];
        if (LNIN) {
            int n = (int)((m0 + r) & 2047);
            v = (v - mu) * rs * lnw[n * 64 + k] + lnb[n * 64 + k];
        }
        xs[k * 128 + r] = v;
    }
    __syncthreads();
    int rbase = warp * 16;
    ull acc[8][CPT];
#pragma unroll
    for (int p = 0; p < 8; p++)
#pragma unroll
        for (int j = 0; j < CPT; j++) acc[p][j] = 0ull;
#pragma unroll 4
    for (int k = 0; k < 64; k++) {
        ull xv[8];
        const float* xp = &xs[k * 128 + rbase];
        lds128(xv[0], xv[1], xp);
        lds128(xv[2], xv[3], xp + 4);
        lds128(xv[4], xv[5], xp + 8);
        lds128(xv[6], xv[7], xp + 12);
        ull wd[CPT];
        if (CPT == 4) {
            float4 w4 = *(const float4*)&wp[(k * 32 + lane) * 4];
            wd[0] = dup2(w4.x); wd[1] = dup2(w4.y); wd[2] = dup2(w4.z); wd[3] = dup2(w4.w);
        } else {
            float2 w2 = *(const float2*)&wp[(k * 32 + lane) * 2];
            wd[0] = dup2(w2.x); wd[1] = dup2(w2.y);
        }
#pragma unroll
        for (int p = 0; p < 8; p++)
#pragma unroll
            for (int j = 0; j < CPT; j++) fma2(acc[p][j], xv[p], wd[j]);
    }
    if (ELR) {
        // feat node-major: [n][bt][128]; block covers one bt slice
        const size_t rowstride = (size_t)8 * TIN * 128;
        size_t base = (size_t)(m0 & 2047) * rowstride + (size_t)(m0 >> 11) * 128;
        float al0 = al[lane], al1 = al[lane + 32], al2v = al[lane + 64], al3 = al[lane + 96];
        float ar0 = ar[lane], ar1 = ar[lane + 32], ar2v = ar[lane + 64], ar3 = ar[lane + 96];
#pragma unroll
        for (int p = 0; p < 8; p++) {
            float2 v0 = unpk2(acc[p][0]);
            float2 v1 = unpk2(acc[p][1]);
            float2 v2 = unpk2(acc[p][2]);
            float2 v3 = unpk2(acc[p][3]);
            size_t a0 = base + (size_t)(rbase + 2 * p) * rowstride;
            size_t a1 = a0 + rowstride;
            out[a0 + lane] = v0.x; out[a0 + lane + 32] = v1.x;
            out[a0 + lane + 64] = v2.x; out[a0 + lane + 96] = v3.x;
            out[a1 + lane] = v0.y; out[a1 + lane + 32] = v1.y;
            out[a1 + lane + 64] = v2.y; out[a1 + lane + 96] = v3.y;
            // attention partials (h0 = cols 0..63, h1 = cols 64..127)
            float sl0x = wred(v0.x * al0 + v1.x * al1);
            float sl1x = wred(v2.x * al2v + v3.x * al3);
            float sr0x = wred(v0.x * ar0 + v1.x * ar1);
            float sr1x = wred(v2.x * ar2v + v3.x * ar3);
            float sl0y = wred(v0.y * al0 + v1.y * al1);
            float sl1y = wred(v2.y * al2v + v3.y * al3);
            float sr0y = wred(v0.y * ar0 + v1.y * ar1);
            float sr1y = wred(v2.y * ar2v + v3.y * ar3);
            if (lane == 0) {
                size_t rA = m0 + rbase + 2 * p;
                el[rA * 2 + 0] = sl0x; el[rA * 2 + 1] = sl1x;
                er[rA * 2 + 0] = sr0x; er[rA * 2 + 1] = sr1x;
                el[(rA + 1) * 2 + 0] = sl0y; el[(rA + 1) * 2 + 1] = sl1y;
                er[(rA + 1) * 2 + 0] = sr0y; er[(rA + 1) * 2 + 1] = sr1y;
            }
        }
    } else {
        float bv0 = bias[lane], bv1 = bias[lane + 32];
#pragma unroll
        for (int p = 0; p < 8; p++) {
            float2 v0 = unpk2(acc[p][0]);
            float2 v1 = unpk2(acc[p][1]);
            size_t r0 = m0 + rbase + 2 * p;
            out[r0 * 64 + lane] = v0.x + bv0;
            out[r0 * 64 + lane + 32] = v1.x + bv1;
            out[(r0 + 1) * 64 + lane] = v0.y + bv0;
            out[(r0 + 1) * 64 + lane + 32] = v1.y + bv1;
        }
    }
}

// ---------------- edge softmax alpha: [e][b][2*TIN] ----------------
template <int TIN>
__global__ void k_alpha(const float* __restrict__ el, const float* __restrict__ er,
                        const int* __restrict__ rowptr, const int* __restrict__ col,
                        float* __restrict__ alpha) {
    const int STR = 2 * TIN;
    int gw = blockIdx.x * 8 + (threadIdx.x >> 5);
    int n = gw >> 3, b = gw & 7;
    int lane = threadIdx.x & 31;
    int r0 = rowptr[n], deg = rowptr[n + 1] - r0;
    const float2* el2 = (const float2*)el;
    const float2* er2 = (const float2*)er;
    if (deg <= 32) {
        int s = (lane < deg) ? col[r0 + lane] : 0;
        float av[STR];
        for (int t = 0; t < TIN; t++) {
            int base = (b * TIN + t) * 2048;
            float2 erd = er2[base + n];
            float2 ela = (lane < deg) ? el2[base + s] : make_float2(-3.0e38f, -3.0e38f);
#pragma unroll
            for (int h = 0; h < 2; h++) {
                float v = (h ? ela.y + erd.y : ela.x + erd.x);
                float e = (lane < deg) ? (v > 0.f ? v : 0.2f * v) : -3.0e38f;
                float mx = e;
                for (int o = 16; o; o >>= 1) mx = fmaxf(mx, __shfl_xor_sync(0xFFFFFFFFu, mx, o));
                float a = (lane < deg) ? __expf(e - mx) : 0.f;
                float sm = a;
                for (int o = 16; o; o >>= 1) sm += __shfl_xor_sync(0xFFFFFFFFu, sm, o);
                av[t * 2 + h] = a / sm;
            }
        }
        if (lane < deg) {
            float4* ap = (float4*)&alpha[((size_t)(r0 + lane) * 8 + b) * STR];
#pragma unroll
            for (int q = 0; q < STR / 4; q++) ap[q] = ((float4*)av)[q];
        }
    } else {
        for (int t = 0; t < TIN; t++) {
            int base = (b * TIN + t) * 2048;
            for (int h = 0; h < 2; h++) {
                float erd = er[(size_t)(base + n) * 2 + h];
                float mx = -3.0e38f;
                for (int j = lane; j < deg; j += 32) {
                    float v = el[(size_t)(base + col[r0 + j]) * 2 + h] + erd;
                    v = v > 0.f ? v : 0.2f * v;
                    mx = fmaxf(mx, v);
                }
                for (int o = 16; o; o >>= 1) mx = fmaxf(mx, __shfl_xor_sync(0xFFFFFFFFu, mx, o));
                float sm = 0.f;
                for (int j = lane; j < deg; j += 32) {
                    float v = el[(size_t)(base + col[r0 + j]) * 2 + h] + erd;
                    v = v > 0.f ? v : 0.2f * v;
                    sm += __expf(v - mx);
                }
                for (int o = 16; o; o >>= 1) sm += __shfl_xor_sync(0xFFFFFFFFu, sm, o);
                for (int j = lane; j < deg; j += 32) {
                    float v = el[(size_t)(base + col[r0 + j]) * 2 + h] + erd;
                    v = v > 0.f ? v : 0.2f * v;
                    alpha[((size_t)(r0 + j) * 8 + b) * STR + t * 2 + h] = __expf(v - mx) / sm;
                }
            }
        }
    }
}

// ---------------- gather: node-major feat, alpha [e][b][STR] ----------------
template <int TIN>
__global__ void k_gather(const float* __restrict__ feat, const float* __restrict__ alpha,
                         const int* __restrict__ rowptr, const int* __restrict__ col,
                         const float* __restrict__ bias, float* __restrict__ y) {
    const int STR = 2 * TIN;
    int n = blockIdx.x, b = blockIdx.y;
    int c = threadIdx.x;  // 64
    int r0 = rowptr[n], deg = rowptr[n + 1] - r0;
    float acc[STR];
#pragma unroll
    for (int i = 0; i < STR; i++) acc[i] = 0.f;
    for (int j = 0; j < deg; j++) {
        int s = col[r0 + j];
        float av[STR];
        const float4* ap = (const float4*)&alpha[((size_t)(r0 + j) * 8 + b) * STR];
#pragma unroll
        for (int q = 0; q < STR / 4; q++) ((float4*)av)[q] = ap[q];  // broadcast
        const float* fp = feat + ((size_t)s * 8 + b) * (TIN * 128) + c;
#pragma unroll
        for (int t = 0; t < TIN; t++) {
#pragma unroll
            for (int h = 0; h < 2; h++)
                acc[t * 2 + h] += av[t * 2 + h] * fp[t * 128 + h * 64];
        }
    }
#pragma unroll
    for (int t = 0; t < TIN; t++) {
#pragma unroll
        for (int h = 0; h < 2; h++) {
            float v = acc[t * 2 + h] + bias[h * 64 + c];
            v = v > 0.f ? v : 0.f;
            y[((size_t)(b * 2 * TIN + t * 2 + h) * 2048 + n) * 64 + c] = v;
        }
    }
}

// ---------------- conv1 (K=5) with fused LN input ----------------
__global__ void k_conv1(const float* __restrict__ z, const float* __restrict__ wt1,
                        const float* __restrict__ tb1, float* __restrict__ o1,
                        const float* __restrict__ lnw, const float* __restrict__ lnb,
                        const double* __restrict__ stat) {
    int b = blockIdx.x >> 8;
    int nt = blockIdx.x & 255;
    int n0 = nt * 8;
    __shared__ float zs[16 * 64 * 8];  // [t][ci][nn]
    __shared__ float muv[16], rsv[16];
    if (threadIdx.x < 16)
        ln_combine(stat, b * 16 + threadIdx.x, muv[threadIdx.x], rsv[threadIdx.x]);
    __syncthreads();
    for (int i = threadIdx.x; i < 8192; i += 256) {
        int t = i >> 9;
        int r = i & 511;
        int nn = r >> 6;
        int ci = r & 63;
        float v = z[((size_t)((b * 16 + t) * 2048 + n0)) * 64 + r];
        v = (v - muv[t]) * rsv[t] * lnw[(size_t)n0 * 64 + r] + lnb[(size_t)n0 * 64 + r];
        zs[(t * 64 + ci) * 8 + nn] = v;
    }
    __syncthreads();
    int colc = threadIdx.x & 15;
    int nnp = (threadIdx.x >> 4) & 3;
    int jg = threadIdx.x >> 6;
    ull acc[4][3];
#pragma unroll
    for (int q = 0; q < 4; q++)
#pragma unroll
        for (int jj = 0; jj < 3; jj++) acc[q][jj] = 0ull;
#pragma unroll
    for (int k = 0; k < 5; k++) {
        for (int ci = 0; ci < 64; ci++) {
            float4 w4 = *(const float4*)&wt1[((k * 64 + ci) * 16 + colc) * 4];
            ull w0 = dup2(w4.x), w1 = dup2(w4.y), w2 = dup2(w4.z), w3 = dup2(w4.w);
#pragma unroll
            for (int jj = 0; jj < 3; jj++) {
                int t = jg * 3 + jj + k;
                ull zv = *(const ull*)&zs[(t * 64 + ci) * 8 + nnp * 2];
                fma2(acc[0][jj], zv, w0);
                fma2(acc[1][jj], zv, w1);
                fma2(acc[2][jj], zv, w2);
                fma2(acc[3][jj], zv, w3);
            }
        }
    }
#pragma unroll
    for (int q = 0; q < 4; q++) {
        int co = q * 16 + colc;
        float bv = tb1[co];
#pragma unroll
        for (int jj = 0; jj < 3; jj++) {
            int j = jg * 3 + jj;
            float2 v = unpk2(acc[q][jj]);
            int n = n0 + nnp * 2;
            o1[((size_t)((b * 12 + j) * 2048 + n)) * 64 + co] = v.x + bv;
            o1[((size_t)((b * 12 + j) * 2048 + n + 1)) * 64 + co] = v.y + bv;
        }
    }
}

// ---------------- final FC (scrambled reshape fused) ----------------
__global__ void k_fc(const float* __restrict__ o2, const float* __restrict__ fw,
                     const float* __restrict__ fb, float* __restrict__ out) {
    int b = blockIdx.x >> 5, q = blockIdx.x & 31;
    __shared__ float s[64 * 64];
    int c = threadIdx.x & 63;
    int rb = threadIdx.x >> 6;
    float acc[3] = {0.f, 0.f, 0.f};
    for (int j = 0; j < 12; j++) {
        __syncthreads();
        for (int i = threadIdx.x; i < 4096; i += 256)
            s[i] = o2[((size_t)((b * 12 + j) * 2048 + q * 64)) * 64 + i];
        __syncthreads();
        for (int rn = 0; rn < 64; rn++) {
            float v = s[rn * 64 + c];
#pragma unroll
            for (int rr = 0; rr < 3; rr++)
                acc[rr] += v * fw[(rb * 3 + rr) * 768 + rn * 12 + j];
        }
    }
    int np = 32 * c + q;
#pragma unroll
    for (int rr = 0; rr < 3; rr++) {
        int r = rb * 3 + rr;
        out[((size_t)b * 2048 + np) * 12 + r] = acc[rr] + fb[r];
    }
}

// ---------------- host ----------------
static void* sym(const void* s) {
    void* p = nullptr;
    cudaGetSymbolAddress(&p, s);
    return p;
}

extern "C" void kernel_launch(void* const* d_in, const int* in_sizes, int n_in,
                              void* d_out, int out_size) {
    const float* x = (const float*)d_in[0];
    const int* src = (const int*)d_in[1];
    const int* dst = (const int*)d_in[2];
    const float* W1 = (const float*)d_in[3];
    const float* al1 = (const float*)d_in[4];
    const float* ar1 = (const float*)d_in[5];
    const float* b1 = (const float*)d_in[6];
    const float* W2 = (const float*)d_in[7];
    const float* al2 = (const float*)d_in[8];
    const float* ar2 = (const float*)d_in[9];
    const float* b2 = (const float*)d_in[10];
    const float* ln1w = (const float*)d_in[11];
    const float* ln1b = (const float*)d_in[12];
    const float* ln2w = (const float*)d_in[13];
    const float* ln2b = (const float*)d_in[14];
    const float* tc1w = (const float*)d_in[15];
    const float* tc1b = (const float*)d_in[16];
    const float* ln3w = (const float*)d_in[17];
    const float* ln3b = (const float*)d_in[18];
    const float* tc2w = (const float*)d_in[19];
    const float* tc2b = (const float*)d_in[20];
    const float* fcw = (const float*)d_in[21];
    const float* fcb = (const float*)d_in[22];
    int E = in_sizes[1];

    float* xT = (float*)sym(g_xT);
    float* feat = (float*)sym(g_feat);
    float* el = (float*)sym(g_el);
    float* er = (float*)sym(g_er);
    float* alpha = (float*)sym(g_alpha);
    float* y = (float*)sym(g_y);
    float* z = (float*)sym(g_z);
    float* o1 = (float*)sym(g_o1);
    float* o2 = (float*)sym(g_o2);
    float* wt1 = (float*)sym(g_wt1);
    float* wp1 = (float*)sym(g_wp1);
    float* wp2 = (float*)sym(g_wp2);
    float* wpt2 = (float*)sym(g_wpt2);
    double* stat = (double*)sym(g_stat);
    int* deg = (int*)sym(g_deg);
    int* cursor = (int*)sym(g_cursor);
    int* rowptr = (int*)sym(g_rowptr);
    int* col = (int*)sym(g_col);
    float* out = (float*)d_out;

    // slots 1-3 setup so capture slot #4 = new gemm1
    k_transpose_x<<<16384, 256>>>(x, xT, deg);                         // 1
    k_count<<<(E + 255) / 256, 256>>>(dst, deg, E);                    // 2
    k_packw128<<<32, 256>>>(W1, wp1);                                  // 3
    k_gemm<128, true, false, 4><<<512, 256>>>(xT, wp1, nullptr, feat,  // 4 <- ncu capture
                                              al1, ar1, el, er, nullptr, nullptr, nullptr);
    k_scan<<<1, 1024>>>(deg, rowptr, cursor);                          // 5
    k_fill_atomic<<<(E + 255) / 256, 256>>>(dst, src, cursor, col, E); // 6
    k_sortcol<<<8, 256>>>(rowptr, col);                                // 7
    k_packw128<<<32, 256>>>(W2, wp2);                                  // 8

    // ---- GAT layer 1 ----
    k_alpha<4><<<2048, 256>>>(el, er, rowptr, col, alpha);
    {
        dim3 g(2048, 8);
        k_gather<4><<<g, 64>>>(feat, alpha, rowptr, col, b1, y);
    }
    k_lnpart<<<256, 1024>>>(y, stat);

    // ---- GAT layer 2 (LN1 fused into GEMM input) ----
    k_gemm<128, true, true, 8><<<1024, 256>>>(y, wp2, nullptr, feat, al2, ar2, el, er,
                                              ln1w, ln1b, stat);
    k_alpha<8><<<2048, 256>>>(el, er, rowptr, col, alpha);
    {
        dim3 g(2048, 8);
        k_gather<8><<<g, 64>>>(feat, alpha, rowptr, col, b2, z);
    }
    k_lnpart<<<512, 1024>>>(z, stat);

    // ---- output layer ----
    k_tw1<<<80, 256>>>(tc1w, wt1);
    k_packw64<<<16, 256>>>(tc2w, wpt2);
    k_conv1<<<2048, 256>>>(z, wt1, tc1b, o1, ln2w, ln2b, stat);  // LN2 fused
    k_lnpart<<<384, 1024>>>(o1, stat);
    k_gemm<64, false, true, 0><<<1536, 256>>>(o1, wpt2, tc2b, o2, nullptr, nullptr, nullptr,
                                              nullptr, ln3w, ln3b, stat);  // LN3 fused
    k_fc<<<256, 256>>>(o2, fcw, fcb, out);
}